// round 15
// baseline (speedup 1.0000x reference)
#include <cuda_runtime.h>
#include <cuda_fp16.h>
#include <math.h>
#include <stdint.h>

#define BATCH 256
#define NT 512
#define DIM 512
#define KTOP 153
#define BKTOK (BATCH*KTOP)      /* 39168 = 306*128 */
#define EDIM 1024
#define NHEADS 8

#define NSTAGE 6
#define GEMM_SMEM (NSTAGE*16384)     /* 6 stages x (A 8KB + B 8KB) = 96KB */
#define ATT_THREADS 320
#define ATT_ROWS 192            /* padded tile rows (3 chunks of 64) */
#define ATT_SMEM (3*ATT_ROWS*64*2)   /* Q,K,V half tiles: 73728 B */

/* ---------------- scratch (device globals; no allocation) ---------------- */
__device__ int    g_idx[BKTOK];
__device__ int    g_lens[BATCH];
__device__ __half g_tokh0[(size_t)BKTOK*DIM];      /* half residual source */
__device__ __half g_qh[(size_t)BKTOK*DIM];         /* LN out (GEMM A) */
__device__ __half g_qkvh[(size_t)BKTOK*3*DIM];     /* half qkv */
__device__ __half g_sa[(size_t)BKTOK*DIM];
__device__ __half g_y1h[(size_t)BKTOK*2*DIM];
__device__ __half g_comb[(size_t)BKTOK*1024];      /* [tok_h | relu_bn_h] */
__device__ __half g_hh[(size_t)BKTOK*DIM];         /* pre-BN h (half) */
__device__ float  g_s1[512];
__device__ float  g_s2[512];
/* half-converted weights */
__device__ __half g_w_sain[1536*512];
__device__ __half g_w_soT[512*512];                /* sa_out_w transposed */
__device__ __half g_w_ref1[1024*512];
__device__ __half g_w_ref2[512*1024];
__device__ __half g_w_mlp1[512*512];
__device__ __half g_w_fin[1024*1024];              /* [lin_w | mlp_w2] */
__device__ __half g_w_fuse[1024*512];              /* W_r1 @ W_so */
__device__ float  g_bias_fin[1024];                /* lin_b + mlp_b2 */
__device__ float  g_bfuse[1024];                   /* W_r1 @ b_so + b_r1 */
__device__ float  g_zero512[512];

/* ------------------------------ helpers ---------------------------------- */
__device__ __forceinline__ uint32_t smem_u32(const void* p) {
    uint32_t a;
    asm("{ .reg .u64 t; cvta.to.shared.u64 t, %1; cvt.u32.u64 %0, t; }"
        : "=r"(a) : "l"(p));
    return a;
}
#define CP_ASYNC16(dst, src) \
    asm volatile("cp.async.cg.shared.global [%0], [%1], 16;" :: "r"(dst), "l"(src))
#define CP_COMMIT()  asm volatile("cp.async.commit_group;" ::: "memory")
#define CP_WAIT_4()  asm volatile("cp.async.wait_group 4;" ::: "memory")

__device__ __forceinline__ void ldsm4(uint32_t& r0, uint32_t& r1,
                                      uint32_t& r2, uint32_t& r3, uint32_t addr) {
    asm volatile("ldmatrix.sync.aligned.m8n8.x4.shared.b16 {%0,%1,%2,%3}, [%4];"
                 : "=r"(r0), "=r"(r1), "=r"(r2), "=r"(r3) : "r"(addr));
}
__device__ __forceinline__ void ldsm4t(uint32_t& r0, uint32_t& r1,
                                       uint32_t& r2, uint32_t& r3, uint32_t addr) {
    asm volatile("ldmatrix.sync.aligned.m8n8.x4.trans.shared.b16 {%0,%1,%2,%3}, [%4];"
                 : "=r"(r0), "=r"(r1), "=r"(r2), "=r"(r3) : "r"(addr));
}
__device__ __forceinline__ void mma_h(float& d0, float& d1, float& d2, float& d3,
                                      uint32_t a0, uint32_t a1, uint32_t a2, uint32_t a3,
                                      uint32_t b0, uint32_t b1)
{
    asm volatile(
        "mma.sync.aligned.m16n8k16.row.col.f32.f16.f16.f32 "
        "{%0,%1,%2,%3}, {%4,%5,%6,%7}, {%8,%9}, {%0,%1,%2,%3};"
        : "+f"(d0), "+f"(d1), "+f"(d2), "+f"(d3)
        : "r"(a0), "r"(a1), "r"(a2), "r"(a3), "r"(b0), "r"(b1));
}
__device__ __forceinline__ uint32_t pack_h2(float a, float b) {
    half2 h = __floats2half2_rn(a, b);
    return *(uint32_t*)&h;
}
/* exact order-independent float atomic max (sign-split trick) */
__device__ __forceinline__ void atomicMaxF(float* a, float v) {
    if (v >= 0.f) atomicMax((int*)a, __float_as_int(v));
    else          atomicMin((unsigned int*)a, __float_as_uint(v));
}

/* -------- merged prep: topk + weight cvt + stats zero + bias + out-init -- */
/* counts in half2 units */
#define P0 393216                 /* sain  1536x512 */
#define P1 (P0+131072)            /* saout  512x512 -> TRANSPOSED g_w_soT */
#define P2 (P1+262144)            /* ref1  1024x512 */
#define P3 (P2+262144)            /* ref2   512x1024 */
#define P4 (P3+262144)            /* lin   1024x512 -> fin cols 0..511 */
#define P5 (P4+131072)            /* mlp1   512x512 */
#define P6 (P5+262144)            /* mlp2  1024x512 -> fin cols 512..1023 */
#define CVT_BLOCKS ((P6 + 511) / 512)      /* 3328 */

__global__ __launch_bounds__(512)
void prep_kernel(const int* __restrict__ text, const float* __restrict__ atten,
                 const float* s_sain, const float* s_saout,
                 const float* s_ref1, const float* s_ref2,
                 const float* s_lin,  const float* s_mlp1, const float* s_mlp2,
                 const float* lin_b,  const float* mlp_b2,
                 float* __restrict__ out)
{
    int t = threadIdx.x;
    if (blockIdx.x < BATCH) {
        /* ---------------- top-k (exact jax.lax.top_k order) -------------- */
        int b = blockIdx.x;
        __shared__ float sval[NT];
        __shared__ int   sidx[NT];
        __shared__ int   red[NT];

        int tv = text[b*NT + t];

        red[t] = (tv << 10) | (NT - 1 - t);
        __syncthreads();
        for (int s = NT/2; s > 0; s >>= 1) {
            if (t < s) red[t] = max(red[t], red[t+s]);
            __syncthreads();
        }
        int eos = NT - 1 - (red[0] & 1023);
        __syncthreads();

        red[t] = (tv != 0) ? 1 : 0;
        __syncthreads();
        for (int s = NT/2; s > 0; s >>= 1) {
            if (t < s) red[t] += red[t+s];
            __syncthreads();
        }
        int nz = red[0];
        __syncthreads();

        float v;
        if (t == 0 || t == eos) v = -1.0f;
        else                    v = atten[((size_t)b*NT + eos)*NT + t];
        if (tv == 0) v = 0.0f;

        sval[t] = v; sidx[t] = t;
        __syncthreads();

        for (int ksz = 2; ksz <= NT; ksz <<= 1) {
            for (int j = ksz >> 1; j > 0; j >>= 1) {
                int ixj = t ^ j;
                if (ixj > t) {
                    float va = sval[t], vb = sval[ixj];
                    int   ia = sidx[t], ib = sidx[ixj];
                    bool aBefore = (va > vb) || (va == vb && ia < ib);
                    bool desc = ((t & ksz) == 0);
                    if (desc ? !aBefore : aBefore) {
                        sval[t] = vb; sval[ixj] = va;
                        sidx[t] = ib; sidx[ixj] = ia;
                    }
                }
                __syncthreads();
            }
        }
        if (t < KTOP) g_idx[b*KTOP + t] = sidx[t];
        if (t == 0) {
            int lnn = nz - 2;
            if (lnn > KTOP) lnn = KTOP;
            if (lnn < 1) lnn = 1;
            g_lens[b] = lnn;
        }
        return;
    }

    int j = blockIdx.x - BATCH;
    if (j == 0) { g_s1[t] = 0.f; g_s2[t] = 0.f; g_zero512[t] = 0.f; }
    if (j == 1) { g_bias_fin[t] = lin_b[t] + mlp_b2[t];
                  g_bias_fin[t+512] = lin_b[t+512] + mlp_b2[t+512]; }
    if (j < 512) out[j * 512 + t] = __int_as_float(0xff800000);

    int i = j * 512 + t;
    if (i >= P6) return;
    if (i < P0) {
        float2 v = ((const float2*)s_sain)[i];
        ((half2*)g_w_sain)[i] = __floats2half2_rn(v.x, v.y);
    } else if (i < P1) {
        int o = i - P0;
        int k = o >> 8, c2 = o & 255;
        float2 v = ((const float2*)s_saout)[o];
        g_w_soT[(2*c2  )*512 + k] = __float2half_rn(v.x);
        g_w_soT[(2*c2+1)*512 + k] = __float2half_rn(v.y);
    } else if (i < P2) {
        int o = i - P1;
        float2 v = ((const float2*)s_ref1)[o];
        ((half2*)g_w_ref1)[o] = __floats2half2_rn(v.x, v.y);
    } else if (i < P3) {
        int o = i - P2;
        float2 v = ((const float2*)s_ref2)[o];
        ((half2*)g_w_ref2)[o] = __floats2half2_rn(v.x, v.y);
    } else if (i < P4) {
        int o = i - P3;
        int n = o >> 8, kk = o & 255;
        float2 v = ((const float2*)s_lin)[o];
        ((half2*)g_w_fin)[n*512 + kk] = __floats2half2_rn(v.x, v.y);
    } else if (i < P5) {
        int o = i - P4;
        float2 v = ((const float2*)s_mlp1)[o];
        ((half2*)g_w_mlp1)[o] = __floats2half2_rn(v.x, v.y);
    } else {
        int o = i - P5;
        int n = o >> 8, kk = o & 255;
        float2 v = ((const float2*)s_mlp2)[o];
        ((half2*)g_w_fin)[n*512 + 256 + kk] = __floats2half2_rn(v.x, v.y);
    }
}

/* ---- fused bias: b_fuse[i] = dot(ref_w1[i,:], sa_out_b) + ref_b1[i] ----- */
__global__ void fuse_bias_kernel(const float* __restrict__ ref_w1,
                                 const float* __restrict__ sa_out_b,
                                 const float* __restrict__ ref_b1)
{
    int row = blockIdx.x;                /* 1024 */
    int t = threadIdx.x;                 /* 128 */
    const float* wr = ref_w1 + (size_t)row * 512;
    float s = 0.f;
#pragma unroll
    for (int q = 0; q < 4; q++) s += wr[t + q*128] * sa_out_b[t + q*128];
    __shared__ float red[128];
    red[t] = s;
    __syncthreads();
    for (int st = 64; st > 0; st >>= 1) {
        if (t < st) red[t] += red[t+st];
        __syncthreads();
    }
    if (t == 0) g_bfuse[row] = red[0] + ref_b1[row];
}

/* ---- fp16 tensor-core GEMM (6-stage cp.async + ldmatrix) ---------------- */
/* 128 threads, 4 warps, warp tile 64x64 (2x2 warp grid over 128x128 tile).  */
/* EPI: 0=bias 1=gelu(bias) 2=C=auxh+sigmoid(g)*(acc+bias) (aux is half)     */
/* OUTH: store half.  STATS: BN column sums.  POOL: fused masked max-pool.   */
template<int EPI, int OUTH, int STATS, int POOL>
__global__ __launch_bounds__(128, 2)
void gemm_h16(const __half* __restrict__ A, int lda,
              const __half* __restrict__ W,
              const float* __restrict__ bias, void* __restrict__ Cout, int ldc,
              int M, int N, int K,
              const void* __restrict__ aux, const float* __restrict__ gptr)
{
    extern __shared__ __half smh[];
    const int tid  = threadIdx.x;
    const int wid  = tid >> 5;           /* 0..3 */
    const int lane = tid & 31;
    const int gid  = lane >> 2;
    const int tig  = lane & 3;
    const int wm   = (wid & 1) * 64;
    const int wn   = (wid >> 1) * 64;
    const int m0   = blockIdx.y * 128;
    const int n0   = blockIdx.x * 128;

    const uint32_t sbase = smem_u32(smh);

    uint32_t sto[4];
    const __half* srcA[4];
    const __half* srcB[4];
#pragma unroll
    for (int q = 0; q < 4; q++) {
        int id  = tid + q * 128;
        int row = id >> 2, cc = id & 3;
        sto[q]  = (uint32_t)(row * 64 + ((cc ^ (row & 3)) << 4));
        srcA[q] = A + (size_t)(m0 + row) * lda + cc * 8;
        srcB[q] = W + (size_t)(n0 + row) * K + cc * 8;
    }

    uint32_t aOff[4], bOff[4];
#pragma unroll
    for (int mt = 0; mt < 4; mt++) {
        int r  = wm + mt * 16 + (lane & 15);
        int ch = lane >> 4;
        aOff[mt] = (uint32_t)(r * 64 + ((ch ^ (r & 3)) << 4));
    }
#pragma unroll
    for (int njp = 0; njp < 4; njp++) {
        int r  = wn + njp * 16 + (lane & 7) + ((lane >> 4) << 3);
        int ch = (lane >> 3) & 1;
        bOff[njp] = (uint32_t)(8192 + r * 64 + ((ch ^ (r & 3)) << 4));
    }

    float acc[4][8][4];
#pragma unroll
    for (int i = 0; i < 4; i++)
#pragma unroll
        for (int j = 0; j < 8; j++)
#pragma unroll
            for (int c = 0; c < 4; c++) acc[i][j][c] = 0.f;

    const int nch = K >> 5;

    auto load_chunk = [&](int c, int s) {
        uint32_t sb = sbase + (uint32_t)s * 16384u;
        size_t ko = (size_t)c * 32;
#pragma unroll
        for (int q = 0; q < 4; q++) {
            CP_ASYNC16(sb + sto[q],        srcA[q] + ko);
            CP_ASYNC16(sb + 8192 + sto[q], srcB[q] + ko);
        }
    };

    /* prologue: 5 chunks */
#pragma unroll
    for (int p = 0; p < 5; p++) { load_chunk(p, p); CP_COMMIT(); }

    int ld_s = 5;      /* next load buffer */
    int cm_s = 0;      /* compute buffer */
    for (int c = 0; c < nch; c++) {
        CP_WAIT_4();
        __syncthreads();
        if (c + 5 < nch) { load_chunk(c + 5, ld_s); if (++ld_s == NSTAGE) ld_s = 0; }
        CP_COMMIT();

        uint32_t stb = sbase + (uint32_t)cm_s * 16384u;
        if (++cm_s == NSTAGE) cm_s = 0;
#pragma unroll
        for (int ks = 0; ks < 2; ks++) {
            const uint32_t kx = (uint32_t)(ks << 5);
            uint32_t af[4][4], bf[4][4];
#pragma unroll
            for (int mt = 0; mt < 4; mt++)
                ldsm4(af[mt][0], af[mt][1], af[mt][2], af[mt][3],
                      stb + (aOff[mt] ^ kx));
#pragma unroll
            for (int njp = 0; njp < 4; njp++)
                ldsm4(bf[njp][0], bf[njp][1], bf[njp][2], bf[njp][3],
                      stb + (bOff[njp] ^ kx));
#pragma unroll
            for (int mt = 0; mt < 4; mt++)
#pragma unroll
                for (int nj = 0; nj < 8; nj++) {
                    const int njp = nj >> 1, pr = (nj & 1) << 1;
                    mma_h(acc[mt][nj][0], acc[mt][nj][1], acc[mt][nj][2], acc[mt][nj][3],
                          af[mt][0], af[mt][1], af[mt][2], af[mt][3],
                          bf[njp][pr], bf[njp][pr + 1]);
                }
        }
    }

    /* -------------------- fused masked max-pool epilogue ----------------- */
    if (POOL) {
        const int base = m0 + wm + gid;
        int bj[8]; bool vj[8];
#pragma unroll
        for (int j = 0; j < 8; j++) {
            int R = base + 8*j;
            int bb = R / KTOP;
            bj[j] = bb;
            vj[j] = (R - bb*KTOP) < g_lens[bb];
        }
        float* outp = (float*)Cout;
        const int bF = bj[0], bL = bj[7];
#pragma unroll
        for (int nj = 0; nj < 8; nj++) {
            int cc = n0 + wn + nj*8 + 2*tig;
            float b0f = bias[cc], b1f = bias[cc + 1];
            float mA0 = -3e38f, mA1 = -3e38f, mB0 = -3e38f, mB1 = -3e38f;
#pragma unroll
            for (int j = 0; j < 8; j++) {
                int mt = j >> 1, rh = (j & 1) << 1;
                float x0 = acc[mt][nj][rh]     + b0f;
                float x1 = acc[mt][nj][rh + 1] + b1f;
                bool sameb = (bj[j] == bF);
                if (vj[j] && sameb)  { mA0 = fmaxf(mA0, x0); mA1 = fmaxf(mA1, x1); }
                if (vj[j] && !sameb) { mB0 = fmaxf(mB0, x0); mB1 = fmaxf(mB1, x1); }
            }
            if (mA0 > -3e38f) atomicMaxF(outp + (size_t)bF*EDIM + cc,     mA0);
            if (mA1 > -3e38f) atomicMaxF(outp + (size_t)bF*EDIM + cc + 1, mA1);
            if (bL != bF) {
                if (mB0 > -3e38f) atomicMaxF(outp + (size_t)bL*EDIM + cc,     mB0);
                if (mB1 > -3e38f) atomicMaxF(outp + (size_t)bL*EDIM + cc + 1, mB1);
            }
        }
        return;
    }

    /* ----------------------------- epilogue ------------------------------ */
    float sg = 0.f;
    if (EPI == 2) sg = 1.0f / (1.0f + expf(-gptr[0]));
    float st1[16], st2[16];
    if (STATS) {
#pragma unroll
        for (int i = 0; i < 16; i++) { st1[i] = 0.f; st2[i] = 0.f; }
    }

#pragma unroll
    for (int mt = 0; mt < 4; mt++) {
#pragma unroll
        for (int nj = 0; nj < 8; nj++) {
            int r  = m0 + wm + mt * 16 + gid;
            int cc = n0 + wn + nj * 8 + 2 * tig;
            float b0v = bias[cc], b1v = bias[cc + 1];
            float v[4];
            v[0] = acc[mt][nj][0] + b0v;
            v[1] = acc[mt][nj][1] + b1v;
            v[2] = acc[mt][nj][2] + b0v;
            v[3] = acc[mt][nj][3] + b1v;
            if (EPI == 1) {
#pragma unroll
                for (int c = 0; c < 4; c++)
                    v[c] = 0.5f * v[c] * (1.0f + erff(v[c] * 0.70710678118654752f));
            }
            if (EPI == 2) {
                const __half* auxh = (const __half*)aux;
                half2 a0 = *(const half2*)(auxh + (size_t)r * N + cc);
                half2 a1 = *(const half2*)(auxh + (size_t)(r + 8) * N + cc);
                v[0] = __low2float(a0)  + sg * v[0];
                v[1] = __high2float(a0) + sg * v[1];
                v[2] = __low2float(a1)  + sg * v[2];
                v[3] = __high2float(a1) + sg * v[3];
            }
            if (STATS) {
                st1[nj*2+0] += v[0] + v[2];
                st1[nj*2+1] += v[1] + v[3];
                st2[nj*2+0] += v[0]*v[0] + v[2]*v[2];
                st2[nj*2+1] += v[1]*v[1] + v[3]*v[3];
            }
            if (OUTH) {
                __half* Ch = (__half*)Cout;
                *(half2*)(Ch + (size_t)r * ldc + cc)       = __floats2half2_rn(v[0], v[1]);
                *(half2*)(Ch + (size_t)(r + 8) * ldc + cc) = __floats2half2_rn(v[2], v[3]);
            } else {
                float* Cf = (float*)Cout;
                *(float2*)(Cf + (size_t)r * ldc + cc)       = make_float2(v[0], v[1]);
                *(float2*)(Cf + (size_t)(r + 8) * ldc + cc) = make_float2(v[2], v[3]);
            }
        }
    }
    if (STATS) {
#pragma unroll
        for (int i = 0; i < 16; i++) {
            float a = st1[i], q = st2[i];
            a += __shfl_xor_sync(0xffffffffu, a, 4);
            a += __shfl_xor_sync(0xffffffffu, a, 8);
            a += __shfl_xor_sync(0xffffffffu, a, 16);
            q += __shfl_xor_sync(0xffffffffu, q, 4);
            q += __shfl_xor_sync(0xffffffffu, q, 8);
            q += __shfl_xor_sync(0xffffffffu, q, 16);
            if (gid == 0) {
                int col = n0 + wn + (i >> 1) * 8 + 2 * tig + (i & 1);
                atomicAdd(&g_s1[col], a);
                atomicAdd(&g_s2[col], q);
            }
        }
    }
}

/* ---------- gather + L2 normalize + LayerNorm (warp per token) ----------- */
__global__ __launch_bounds__(256)
void gather_ln_kernel(const float* __restrict__ features,
                      const float* __restrict__ lnw,
                      const float* __restrict__ lnb)
{
    int warp = threadIdx.x >> 5;
    int lane = threadIdx.x & 31;
    int token = blockIdx.x * 8 + warp;           /* BKTOK = 4896*8 exact */
    int b = token / KTOP;
    int src = g_idx[token];
    const float* f = features + ((size_t)b*NT + src)*DIM;

    float4 v[4];
    float s1 = 0.f, s2 = 0.f;
#pragma unroll
    for (int q = 0; q < 4; q++) {
        v[q] = *(const float4*)(f + lane*4 + q*128);
        s1 += v[q].x + v[q].y + v[q].z + v[q].w;
        s2 += v[q].x*v[q].x + v[q].y*v[q].y + v[q].z*v[q].z + v[q].w*v[q].w;
    }
#pragma unroll
    for (int st = 16; st > 0; st >>= 1) {
        s1 += __shfl_xor_sync(0xffffffffu, s1, st);
        s2 += __shfl_xor_sync(0xffffffffu, s2, st);
    }
    float inv  = 1.0f / (sqrtf(s2) + 1e-6f);
    float mean = s1 * inv * (1.0f/DIM);
    float et2  = s2 * inv * inv * (1.0f/DIM);
    float var  = et2 - mean*mean;
    float rstd = rsqrtf(var + 1e-5f);

    __half* tokp = g_tokh0 + (size_t)token*DIM;
    __half* qp   = g_qh    + (size_t)token*DIM;
#pragma unroll
    for (int q = 0; q < 4; q++) {
        int c = lane*4 + q*128;
        float4 w4 = *(const float4*)(lnw + c);
        float4 b4 = *(const float4*)(lnb + c);
        float t0 = v[q].x * inv, t1 = v[q].y * inv;
        float t2 = v[q].z * inv, t3 = v[q].w * inv;
        *(half2*)(tokp + c)     = __floats2half2_rn(t0, t1);
        *(half2*)(tokp + c + 2) = __floats2half2_rn(t2, t3);
        half2 h0 = __floats2half2_rn((t0-mean)*rstd*w4.x + b4.x,
                                     (t1-mean)*rstd*w4.y + b4.y);
        half2 h1 = __floats2half2_rn((t2-mean)*rstd*w4.z + b4.z,
                                     (t3-mean)*rstd*w4.w + b4.w);
        *(half2*)(qp + c)     = h0;
        *(half2*)(qp + c + 2) = h1;
    }
}

/* ------------- tensor-core flash attention: one block per (b,h) ---------- */
__global__ __launch_bounds__(ATT_THREADS)
void attn_tc()
{
    const int h = blockIdx.x, b = blockIdx.y;
    extern __shared__ __half ash[];
    __half* sQ = ash;
    __half* sK = ash + ATT_ROWS*64;
    __half* sV = ash + 2*ATT_ROWS*64;
    const int tid = threadIdx.x;
    const int wid = tid >> 5, lane = tid & 31;
    const int gid = lane >> 2, tig = lane & 3;
    const size_t tokbase = (size_t)b * KTOP;
    const __half* qkv = g_qkvh;

    for (int i = tid; i < ATT_ROWS*8; i += ATT_THREADS) {
        int r = i >> 3, c = i & 7;
        uint4 zq = make_uint4(0,0,0,0), zk = zq, zv = zq;
        if (r < KTOP) {
            const __half* base = qkv + (tokbase + r)*1536 + h*64 + c*8;
            zq = *(const uint4*)(base);
            zk = *(const uint4*)(base + 512);
            zv = *(const uint4*)(base + 1024);
        }
        int off = r*64 + ((c ^ (r & 7)) << 3);
        *(uint4*)(sQ + off) = zq;
        *(uint4*)(sK + off) = zk;
        *(uint4*)(sV + off) = zv;
    }
    __syncthreads();

    const uint32_t uQ = smem_u32(sQ), uK = smem_u32(sK), uV = smem_u32(sV);
    const int wm = wid * 16;
    const int mrow = lane & 7, msel = lane >> 3;

    uint32_t aq[4][4];
    {
        int row = wm + mrow + ((msel & 1) << 3);
        int chalf = msel >> 1;
#pragma unroll
        for (int ks = 0; ks < 4; ks++) {
            int ch = 2*ks + chalf;
            ldsm4(aq[ks][0], aq[ks][1], aq[ks][2], aq[ks][3],
                  uQ + (uint32_t)(row*128 + ((ch ^ (row & 7)) << 4)));
        }
    }

    float mr0 = -1e30f, mr1 = -1e30f, l0 = 0.f, l1 = 0.f;
    float o[8][4];
#pragma unroll
    for (int i = 0; i < 8; i++)
#pragma unroll
        for (int c = 0; c < 4; c++) o[i][c] = 0.f;

#pragma unroll 1
    for (int kc = 0; kc < 3; kc++) {
        float sS[8][4];
#pragma unroll
        for (int i = 0; i < 8; i++)
#pragma unroll
            for (int c = 0; c < 4; c++) sS[i][c] = 0.f;

#pragma unroll
        for (int ks = 0; ks < 4; ks++) {
            int chalf = msel >> 1;
            int ch = 2*ks + chalf;
            int nro = mrow + ((msel & 1) << 3);
#pragma unroll
            for (int p = 0; p < 4; p++) {
                int nr = kc*64 + p*16 + nro;
                uint32_t r0, r1, r2, r3;
                ldsm4(r0, r1, r2, r3,
                      uK + (uint32_t)(nr*128 + ((ch ^ (nr & 7)) << 4)));
                mma_h(sS[2*p][0], sS[2*p][1], sS[2*p][2], sS[2*p][3],
                      aq[ks][0], aq[ks][1], aq[ks][2], aq[ks][3], r0, r2);
                mma_h(sS[2*p+1][0], sS[2*p+1][1], sS[2*p+1][2], sS[2*p+1][3],
                      aq[ks][0], aq[ks][1], aq[ks][2], aq[ks][3], r1, r3);
            }
        }

#pragma unroll
        for (int nf = 0; nf < 8; nf++)
#pragma unroll
            for (int c = 0; c < 4; c++) sS[nf][c] *= 0.125f;
        if (kc == 2) {
#pragma unroll
            for (int nf = 0; nf < 8; nf++) {
                int col = 128 + nf*8 + 2*tig;
                if (col     >= KTOP) { sS[nf][0] = -1e30f; sS[nf][2] = -1e30f; }
                if (col + 1 >= KTOP) { sS[nf][1] = -1e30f; sS[nf][3] = -1e30f; }
            }
        }

        float cm0 = -1e30f, cm1 = -1e30f;
#pragma unroll
        for (int nf = 0; nf < 8; nf++) {
            cm0 = fmaxf(cm0, fmaxf(sS[nf][0], sS[nf][1]));
            cm1 = fmaxf(cm1, fmaxf(sS[nf][2], sS[nf][3]));
        }
        cm0 = fmaxf(cm0, __shfl_xor_sync(0xffffffffu, cm0, 1));
        cm0 = fmaxf(cm0, __shfl_xor_sync(0xffffffffu, cm0, 2));
        cm1 = fmaxf(cm1, __shfl_xor_sync(0xffffffffu, cm1, 1));
        cm1 = fmaxf(cm1, __shfl_xor_sync(0xffffffffu, cm1, 2));
        float nm0 = fmaxf(mr0, cm0), nm1 = fmaxf(mr1, cm1);
        float f0 = __expf(mr0 - nm0), f1 = __expf(mr1 - nm1);
        mr0 = nm0; mr1 = nm1;

        float ls0 = 0.f, ls1 = 0.f;
#pragma unroll
        for (int nf = 0; nf < 8; nf++) {
            sS[nf][0] = __expf(sS[nf][0] - nm0);
            sS[nf][1] = __expf(sS[nf][1] - nm0);
            sS[nf][2] = __expf(sS[nf][2] - nm1);
            sS[nf][3] = __expf(sS[nf][3] - nm1);
            ls0 += sS[nf][0] + sS[nf][1];
            ls1 += sS[nf][2] + sS[nf][3];
        }
        ls0 += __shfl_xor_sync(0xffffffffu, ls0, 1);
        ls0 += __shfl_xor_sync(0xffffffffu, ls0, 2);
        ls1 += __shfl_xor_sync(0xffffffffu, ls1, 1);
        ls1 += __shfl_xor_sync(0xffffffffu, ls1, 2);
        l0 = l0*f0 + ls0;
        l1 = l1*f1 + ls1;
#pragma unroll
        for (int df = 0; df < 8; df++) {
            o[df][0] *= f0; o[df][1] *= f0;
            o[df][2] *= f1; o[df][3] *= f1;
        }

        uint32_t ap[4][4];
#pragma unroll
        for (int j = 0; j < 4; j++) {
            ap[j][0] = pack_h2(sS[2*j][0],   sS[2*j][1]);
            ap[j][1] = pack_h2(sS[2*j][2],   sS[2*j][3]);
            ap[j][2] = pack_h2(sS[2*j+1][0], sS[2*j+1][1]);
            ap[j][3] = pack_h2(sS[2*j+1][2], sS[2*j+1][3]);
        }

#pragma unroll
        for (int j = 0; j < 4; j++) {
            int kr = kc*64 + j*16 + mrow + ((msel & 1) << 3);
            int chalf = msel >> 1;
#pragma unroll
            for (int p = 0; p < 4; p++) {
                int ch = 2*p + chalf;
                uint32_t r0, r1, r2, r3;
                ldsm4t(r0, r1, r2, r3,
                       uV + (uint32_t)(kr*128 + ((ch ^ (kr & 7)) << 4)));
                mma_h(o[2*p][0], o[2*p][1], o[2*p][2], o[2*p][3],
                      ap[j][0], ap[j][1], ap[j][2], ap[j][3], r0, r1);
                mma_h(o[2*p+1][0], o[2*p+1][1], o[2*p+1][2], o[2*p+1][3],
                      ap[j][0], ap[j][1], ap[j][2], ap[j][3], r2, r3);
            }
        }
    }

    float inv0 = 1.0f / l0, inv1 = 1.0f / l1;
    int r0g = wm + gid, r1g = wm + gid + 8;
#pragma unroll
    for (int df = 0; df < 8; df++) {
        int d = df*8 + 2*tig;
        if (r0g < KTOP)
            *(half2*)(g_sa + (tokbase + r0g)*512 + h*64 + d) =
                __floats2half2_rn(o[df][0]*inv0, o[df][1]*inv0);
        if (r1g < KTOP)
            *(half2*)(g_sa + (tokbase + r1g)*512 + h*64 + d) =
                __floats2half2_rn(o[df][2]*inv1, o[df][3]*inv1);
    }
}

/* ------------- BatchNorm apply (stats finalized inline) ------------------ */
__global__ void bn_apply(const float* __restrict__ bnw, const float* __restrict__ bnb)
{
    size_t i = (size_t)blockIdx.x*256 + threadIdx.x;   /* over BKTOK*256 h2 */
    if (i < (size_t)BKTOK*256) {
        int c2 = (int)(i & 255);
        int c  = c2 * 2;
        size_t row = i >> 8;
        float m0 = g_s1[c  ] * (1.0f/BKTOK);
        float m1 = g_s1[c+1] * (1.0f/BKTOK);
        float r0 = rsqrtf(g_s2[c  ] * (1.0f/BKTOK) - m0*m0 + 1e-5f);
        float r1 = rsqrtf(g_s2[c+1] * (1.0f/BKTOK) - m1*m1 + 1e-5f);
        half2 hv = ((const half2*)g_hh)[i];
        float x0 = __low2float(hv), x1 = __high2float(hv);
        x0 = (x0 - m0) * r0 * bnw[c  ] + bnb[c  ];
        x1 = (x1 - m1) * r1 * bnw[c+1] + bnb[c+1];
        ((half2*)(g_comb + row*1024 + 512))[c2] =
            __floats2half2_rn(fmaxf(x0, 0.f), fmaxf(x1, 0.f));
    }
}

/* ------------------------------- launcher -------------------------------- */
extern "C" void kernel_launch(void* const* d_in, const int* in_sizes, int n_in,
                              void* d_out, int out_size)
{
    const float* features = (const float*)d_in[0];
    const int*   text     = (const int*)  d_in[1];
    const float* atten    = (const float*)d_in[2];
    const float* ln_q_w   = (const float*)d_in[3];
    const float* ln_q_b   = (const float*)d_in[4];
    const float* sa_in_w  = (const float*)d_in[5];
    const float* sa_in_b  = (const float*)d_in[6];
    const float* sa_out_w = (const float*)d_in[7];
    const float* sa_out_b = (const float*)d_in[8];
    const float* ref_w1   = (const float*)d_in[9];
    const float* ref_b1   = (const float*)d_in[10];
    const float* ref_w2   = (const float*)d_in[11];
    const float* ref_b2   = (const float*)d_in[12];
    const float* gscal    = (const float*)d_in[13];
    const float* lin_w    = (const float*)d_in[14];
    const float* lin_b    = (const float*)d_in[15];
    const float* mlp_w1   = (const float*)d_in[16];
    const float* mlp_b1   = (const float*)d_in[17];
    const float* bn_w     = (const float*)d_in[18];
    const float* bn_b     = (const float*)d_in[19];
    const float* mlp_w2   = (const float*)d_in[20];
    const float* mlp_b2   = (const float*)d_in[21];
    float* out = (float*)d_out;

    float *p_bfin, *p_bfuse, *p_zero;
    __half *p_tok0, *p_qh, *p_qkvh, *p_sa, *p_y1h, *p_comb, *p_hh;
    __half *w_sain, *w_soT, *w_ref1, *w_ref2, *w_mlp1, *w_fin, *w_fuse;
    cudaGetSymbolAddress((void**)&p_tok0, g_tokh0);
    cudaGetSymbolAddress((void**)&p_qh,   g_qh);
    cudaGetSymbolAddress((void**)&p_qkvh, g_qkvh);
    cudaGetSymbolAddress((void**)&p_sa,   g_sa);
    cudaGetSymbolAddress((void**)&p_y1h,  g_y1h);
    cudaGetSymbolAddress((void**)&p_comb, g_comb);
    cudaGetSymbolAddress((void**)&p_hh,   g_hh);
    cudaGetSymbolAddress((void**)&p_bfin, g_bias_fin);
    cudaGetSymbolAddress((void**)&p_bfuse, g_bfuse);
    cudaGetSymbolAddress((void**)&p_zero, g_zero512);
    cudaGetSymbolAddress((void**)&w_sain,  g_w_sain);
    cudaGetSymbolAddress((void**)&w_soT,   g_w_soT);
    cudaGetSymbolAddress((void**)&w_ref1,  g_w_ref1);
    cudaGetSymbolAddress((void**)&w_ref2,  g_w_ref2);
    cudaGetSymbolAddress((void**)&w_mlp1,  g_w_mlp1);
    cudaGetSymbolAddress((void**)&w_fin,   g_w_fin);
    cudaGetSymbolAddress((void**)&w_fuse,  g_w_fuse);

    cudaFuncSetAttribute(gemm_h16<0,1,0,0>, cudaFuncAttributeMaxDynamicSharedMemorySize, GEMM_SMEM);
    cudaFuncSetAttribute(gemm_h16<0,1,1,0>, cudaFuncAttributeMaxDynamicSharedMemorySize, GEMM_SMEM);
    cudaFuncSetAttribute(gemm_h16<1,1,0,0>, cudaFuncAttributeMaxDynamicSharedMemorySize, GEMM_SMEM);
    cudaFuncSetAttribute(gemm_h16<2,1,0,0>, cudaFuncAttributeMaxDynamicSharedMemorySize, GEMM_SMEM);
    cudaFuncSetAttribute(gemm_h16<0,0,0,1>, cudaFuncAttributeMaxDynamicSharedMemorySize, GEMM_SMEM);
    cudaFuncSetAttribute(attn_tc, cudaFuncAttributeMaxDynamicSharedMemorySize, ATT_SMEM);

    const int MROWS = BKTOK;             /* 39168 = 306*128 */

    /* merged: topk + weight cvt + stats zero + fused bias + out -inf init */
    prep_kernel<<<BATCH + CVT_BLOCKS, 512>>>(text, atten,
        sa_in_w, sa_out_w, ref_w1, ref_w2, lin_w, mlp_w1, mlp_w2,
        lin_b, mlp_b2, out);
    /* W_fuse = W_r1 @ W_so */
    gemm_h16<0,1,0,0><<<dim3(512/128, 1024/128), 128, GEMM_SMEM>>>(
        w_ref1, 512, w_soT, p_zero, w_fuse, 512, 1024, 512, 512, nullptr, nullptr);
    fuse_bias_kernel<<<1024, 128>>>(ref_w1, sa_out_b, ref_b1);

    gather_ln_kernel<<<BKTOK/8, 256>>>(features, ln_q_w, ln_q_b);

    /* qkv = LN(tok) @ sa_in_w^T + b  (half out) */
    gemm_h16<0,1,0,0><<<dim3(1536/128, MROWS/128), 128, GEMM_SMEM>>>(
        p_qh, 512, w_sain, sa_in_b, p_qkvh, 1536, MROWS, 1536, 512, nullptr, nullptr);
    attn_tc<<<dim3(NHEADS, BATCH), ATT_THREADS, ATT_SMEM>>>();

    /* y1 = gelu(sa @ W_fuse^T + b_fuse)  (half out) */
    gemm_h16<1,1,0,0><<<dim3(1024/128, MROWS/128), 128, GEMM_SMEM>>>(
        p_sa, 512, w_fuse, p_bfuse, p_y1h, 1024, MROWS, 1024, 512, nullptr, nullptr);
    /* comb[:,0:512] = tok_h + sigmoid(g)*(y1 @ ref_w2^T + b)  (half out) */
    gemm_h16<2,1,0,0><<<dim3(512/128, MROWS/128), 128, GEMM_SMEM>>>(
        p_y1h, 1024, w_ref2, ref_b2, p_comb, 1024, MROWS, 512, 1024, p_tok0, gscal);
    /* h = tok_h @ mlp_w1^T + b  (half out + fused BN stats) */
    gemm_h16<0,1,1,0><<<dim3(512/128, MROWS/128), 128, GEMM_SMEM>>>(
        p_comb, 1024, w_mlp1, mlp_b1, p_hh, 512, MROWS, 512, 512, nullptr, nullptr);
    bn_apply<<<(int)(((size_t)BKTOK*256 + 255)/256), 256>>>(bn_w, bn_b);

    /* feat GEMM with fused masked max-pool -> out (atomicMax) */
    gemm_h16<0,0,0,1><<<dim3(1024/128, MROWS/128), 128, GEMM_SMEM>>>(
        p_comb, 1024, w_fin, p_bfin, out, 1024, MROWS, 1024, 1024, nullptr, nullptr);
}

// round 16
// speedup vs baseline: 1.0212x; 1.0212x over previous
#include <cuda_runtime.h>
#include <cuda_fp16.h>
#include <math.h>
#include <stdint.h>

#define BATCH 256
#define NT 512
#define DIM 512
#define KTOP 153
#define BKTOK (BATCH*KTOP)      /* 39168 = 306*128 */
#define EDIM 1024
#define NHEADS 8

#define GEMM_SMEM (4*16384)     /* 4 stages x (A 8KB + B 8KB) */
#define ATT_THREADS 320
#define ATT_ROWS 192            /* padded tile rows (3 chunks of 64) */
#define ATT_SMEM (3*ATT_ROWS*64*2)   /* Q,K,V half tiles: 73728 B */

/* ---------------- scratch (device globals; no allocation) ---------------- */
__device__ int    g_idx[BKTOK];
__device__ int    g_lens[BATCH];
__device__ __half g_tokh0[(size_t)BKTOK*DIM];      /* half residual source */
__device__ __half g_qh[(size_t)BKTOK*DIM];         /* LN out (GEMM A) */
__device__ __half g_qkvh[(size_t)BKTOK*3*DIM];     /* half qkv */
__device__ __half g_sa[(size_t)BKTOK*DIM];
__device__ __half g_y1h[(size_t)BKTOK*2*DIM];
__device__ __half g_comb[(size_t)BKTOK*1024];      /* [tok_h | relu_bn_h] */
__device__ __half g_hh[(size_t)BKTOK*DIM];         /* pre-BN h (half) */
__device__ float  g_s1[512];
__device__ float  g_s2[512];
/* half-converted weights */
__device__ __half g_w_sain[1536*512];
__device__ __half g_w_soT[512*512];                /* sa_out_w transposed */
__device__ __half g_w_ref1[1024*512];
__device__ __half g_w_ref2[512*1024];
__device__ __half g_w_mlp1[512*512];
__device__ __half g_w_fin[1024*1024];              /* [lin_w | mlp_w2] */
__device__ __half g_w_fuse[1024*512];              /* W_r1 @ W_so */
__device__ float  g_bias_fin[1024];                /* lin_b + mlp_b2 */
__device__ float  g_bfuse[1024];                   /* W_r1 @ b_so + b_r1 */
__device__ float  g_zero512[512];

/* ------------------------------ helpers ---------------------------------- */
__device__ __forceinline__ uint32_t smem_u32(const void* p) {
    uint32_t a;
    asm("{ .reg .u64 t; cvta.to.shared.u64 t, %1; cvt.u32.u64 %0, t; }"
        : "=r"(a) : "l"(p));
    return a;
}
#define CP_ASYNC16(dst, src) \
    asm volatile("cp.async.cg.shared.global [%0], [%1], 16;" :: "r"(dst), "l"(src))
#define CP_COMMIT()  asm volatile("cp.async.commit_group;" ::: "memory")
#define CP_WAIT_2()  asm volatile("cp.async.wait_group 2;" ::: "memory")

__device__ __forceinline__ void ldsm4(uint32_t& r0, uint32_t& r1,
                                      uint32_t& r2, uint32_t& r3, uint32_t addr) {
    asm volatile("ldmatrix.sync.aligned.m8n8.x4.shared.b16 {%0,%1,%2,%3}, [%4];"
                 : "=r"(r0), "=r"(r1), "=r"(r2), "=r"(r3) : "r"(addr));
}
__device__ __forceinline__ void ldsm4t(uint32_t& r0, uint32_t& r1,
                                       uint32_t& r2, uint32_t& r3, uint32_t addr) {
    asm volatile("ldmatrix.sync.aligned.m8n8.x4.trans.shared.b16 {%0,%1,%2,%3}, [%4];"
                 : "=r"(r0), "=r"(r1), "=r"(r2), "=r"(r3) : "r"(addr));
}
__device__ __forceinline__ void mma_h(float& d0, float& d1, float& d2, float& d3,
                                      uint32_t a0, uint32_t a1, uint32_t a2, uint32_t a3,
                                      uint32_t b0, uint32_t b1)
{
    asm volatile(
        "mma.sync.aligned.m16n8k16.row.col.f32.f16.f16.f32 "
        "{%0,%1,%2,%3}, {%4,%5,%6,%7}, {%8,%9}, {%0,%1,%2,%3};"
        : "+f"(d0), "+f"(d1), "+f"(d2), "+f"(d3)
        : "r"(a0), "r"(a1), "r"(a2), "r"(a3), "r"(b0), "r"(b1));
}
__device__ __forceinline__ uint32_t pack_h2(float a, float b) {
    half2 h = __floats2half2_rn(a, b);
    return *(uint32_t*)&h;
}
/* exact order-independent float atomic max (sign-split trick) */
__device__ __forceinline__ void atomicMaxF(float* a, float v) {
    if (v >= 0.f) atomicMax((int*)a, __float_as_int(v));
    else          atomicMin((unsigned int*)a, __float_as_uint(v));
}

/* -- weight cvt + stats zero + bias sums + out-init + fused-bias rows ----- */
/* counts in half2 units */
#define P0 393216                 /* sain  1536x512 */
#define P1 (P0+131072)            /* saout  512x512 -> TRANSPOSED g_w_soT */
#define P2 (P1+262144)            /* ref1  1024x512 */
#define P3 (P2+262144)            /* ref2   512x1024 */
#define P4 (P3+262144)            /* lin   1024x512 -> fin cols 0..511 */
#define P5 (P4+131072)            /* mlp1   512x512 */
#define P6 (P5+262144)            /* mlp2  1024x512 -> fin cols 512..1023 */
#define CVTB ((P6 + 255) / 256)   /* 6656 */

__global__ void cvt_all_kernel(const float* s_sain, const float* s_saout,
                               const float* s_ref1, const float* s_ref2,
                               const float* s_lin,  const float* s_mlp1,
                               const float* s_mlp2,
                               const float* lin_b,  const float* mlp_b2,
                               const float* sa_out_b, const float* ref_b1,
                               float* __restrict__ out)
{
    int t = threadIdx.x;
    if (blockIdx.x >= CVTB) {
        /* fused-bias rows: b_fuse[row] = dot(ref_w1[row,:], sa_out_b) + ref_b1[row] */
        int row = blockIdx.x - CVTB;         /* 0..1023 */
        const float* wr = s_ref1 + (size_t)row * 512;
        float s = wr[t] * sa_out_b[t] + wr[t + 256] * sa_out_b[t + 256];
        __shared__ float red[256];
        red[t] = s;
        __syncthreads();
        for (int st = 128; st > 0; st >>= 1) {
            if (t < st) red[t] += red[t + st];
            __syncthreads();
        }
        if (t == 0) g_bfuse[row] = red[0] + ref_b1[row];
        return;
    }
    if (blockIdx.x == 0) {
        g_s1[t] = 0.f; g_s1[t+256] = 0.f;
        g_s2[t] = 0.f; g_s2[t+256] = 0.f;
        g_zero512[t] = 0.f; g_zero512[t+256] = 0.f;
    }
    if (blockIdx.x == 1) {
#pragma unroll
        for (int q = 0; q < 4; q++)
            g_bias_fin[t + q*256] = lin_b[t + q*256] + mlp_b2[t + q*256];
    }
    if (blockIdx.x < BATCH*EDIM/256)     /* init out to -inf (fused pool) */
        out[blockIdx.x * 256 + t] = __int_as_float(0xff800000);

    int i = blockIdx.x * 256 + t;
    if (i >= P6) return;
    if (i < P0) {
        float2 v = ((const float2*)s_sain)[i];
        ((half2*)g_w_sain)[i] = __floats2half2_rn(v.x, v.y);
    } else if (i < P1) {
        int o = i - P0;
        int k = o >> 8, c2 = o & 255;
        float2 v = ((const float2*)s_saout)[o];
        g_w_soT[(2*c2  )*512 + k] = __float2half_rn(v.x);
        g_w_soT[(2*c2+1)*512 + k] = __float2half_rn(v.y);
    } else if (i < P2) {
        int o = i - P1;
        float2 v = ((const float2*)s_ref1)[o];
        ((half2*)g_w_ref1)[o] = __floats2half2_rn(v.x, v.y);
    } else if (i < P3) {
        int o = i - P2;
        float2 v = ((const float2*)s_ref2)[o];
        ((half2*)g_w_ref2)[o] = __floats2half2_rn(v.x, v.y);
    } else if (i < P4) {
        int o = i - P3;
        int n = o >> 8, kk = o & 255;
        float2 v = ((const float2*)s_lin)[o];
        ((half2*)g_w_fin)[n*512 + kk] = __floats2half2_rn(v.x, v.y);
    } else if (i < P5) {
        int o = i - P4;
        float2 v = ((const float2*)s_mlp1)[o];
        ((half2*)g_w_mlp1)[o] = __floats2half2_rn(v.x, v.y);
    } else {
        int o = i - P5;
        int n = o >> 8, kk = o & 255;
        float2 v = ((const float2*)s_mlp2)[o];
        ((half2*)g_w_fin)[n*512 + 256 + kk] = __floats2half2_rn(v.x, v.y);
    }
}

/* ---- fp16 tensor-core GEMM (cp.async + ldmatrix): C = A @ W^T + bias ---- */
/* 128 threads, 4 warps, warp tile 64x64 (2x2 warp grid over 128x128 tile).  */
/* EPI: 0=bias 1=gelu(bias) 2=C=auxh+sigmoid(g)*(acc+bias) (aux is half)     */
/* OUTH: store half.  STATS: BN column sums.  POOL: fused masked max-pool.   */
template<int EPI, int OUTH, int STATS, int POOL>
__global__ __launch_bounds__(128, 2)
void gemm_h16(const __half* __restrict__ A, int lda,
              const __half* __restrict__ W,
              const float* __restrict__ bias, void* __restrict__ Cout, int ldc,
              int M, int N, int K,
              const void* __restrict__ aux, const float* __restrict__ gptr)
{
    extern __shared__ __half smh[];
    const int tid  = threadIdx.x;
    const int wid  = tid >> 5;           /* 0..3 */
    const int lane = tid & 31;
    const int gid  = lane >> 2;
    const int tig  = lane & 3;
    const int wm   = (wid & 1) * 64;
    const int wn   = (wid >> 1) * 64;
    const int m0   = blockIdx.y * 128;
    const int n0   = blockIdx.x * 128;

    const uint32_t sbase = smem_u32(smh);

    uint32_t sto[4];
    const __half* srcA[4];
    const __half* srcB[4];
#pragma unroll
    for (int q = 0; q < 4; q++) {
        int id  = tid + q * 128;
        int row = id >> 2, cc = id & 3;
        sto[q]  = (uint32_t)(row * 64 + ((cc ^ (row & 3)) << 4));
        srcA[q] = A + (size_t)(m0 + row) * lda + cc * 8;
        srcB[q] = W + (size_t)(n0 + row) * K + cc * 8;
    }

    uint32_t aOff[4], bOff[4];
#pragma unroll
    for (int mt = 0; mt < 4; mt++) {
        int r  = wm + mt * 16 + (lane & 15);
        int ch = lane >> 4;
        aOff[mt] = (uint32_t)(r * 64 + ((ch ^ (r & 3)) << 4));
    }
#pragma unroll
    for (int njp = 0; njp < 4; njp++) {
        int r  = wn + njp * 16 + (lane & 7) + ((lane >> 4) << 3);
        int ch = (lane >> 3) & 1;
        bOff[njp] = (uint32_t)(8192 + r * 64 + ((ch ^ (r & 3)) << 4));
    }

    float acc[4][8][4];
#pragma unroll
    for (int i = 0; i < 4; i++)
#pragma unroll
        for (int j = 0; j < 8; j++)
#pragma unroll
            for (int c = 0; c < 4; c++) acc[i][j][c] = 0.f;

    const int nch = K >> 5;

    auto load_chunk = [&](int c) {
        uint32_t sb = sbase + (uint32_t)(c & 3) * 16384u;
        size_t ko = (size_t)c * 32;
#pragma unroll
        for (int q = 0; q < 4; q++) {
            CP_ASYNC16(sb + sto[q],        srcA[q] + ko);
            CP_ASYNC16(sb + 8192 + sto[q], srcB[q] + ko);
        }
    };

    load_chunk(0); CP_COMMIT();
    load_chunk(1); CP_COMMIT();
    load_chunk(2); CP_COMMIT();

    for (int c = 0; c < nch; c++) {
        CP_WAIT_2();
        __syncthreads();
        if (c + 3 < nch) load_chunk(c + 3);
        CP_COMMIT();

        uint32_t stb = sbase + (uint32_t)(c & 3) * 16384u;
#pragma unroll
        for (int ks = 0; ks < 2; ks++) {
            const uint32_t kx = (uint32_t)(ks << 5);
            uint32_t af[4][4], bf[4][4];
#pragma unroll
            for (int mt = 0; mt < 4; mt++)
                ldsm4(af[mt][0], af[mt][1], af[mt][2], af[mt][3],
                      stb + (aOff[mt] ^ kx));
#pragma unroll
            for (int njp = 0; njp < 4; njp++)
                ldsm4(bf[njp][0], bf[njp][1], bf[njp][2], bf[njp][3],
                      stb + (bOff[njp] ^ kx));
#pragma unroll
            for (int mt = 0; mt < 4; mt++)
#pragma unroll
                for (int nj = 0; nj < 8; nj++) {
                    const int njp = nj >> 1, pr = (nj & 1) << 1;
                    mma_h(acc[mt][nj][0], acc[mt][nj][1], acc[mt][nj][2], acc[mt][nj][3],
                          af[mt][0], af[mt][1], af[mt][2], af[mt][3],
                          bf[njp][pr], bf[njp][pr + 1]);
                }
        }
    }

    /* -------------------- fused masked max-pool epilogue ----------------- */
    if (POOL) {
        const int base = m0 + wm + gid;
        int bj[8]; bool vj[8];
#pragma unroll
        for (int j = 0; j < 8; j++) {
            int R = base + 8*j;
            int bb = R / KTOP;
            bj[j] = bb;
            vj[j] = (R - bb*KTOP) < g_lens[bb];
        }
        float* outp = (float*)Cout;
        const int bF = bj[0], bL = bj[7];
#pragma unroll
        for (int nj = 0; nj < 8; nj++) {
            int cc = n0 + wn + nj*8 + 2*tig;
            float b0f = bias[cc], b1f = bias[cc + 1];
            float mA0 = -3e38f, mA1 = -3e38f, mB0 = -3e38f, mB1 = -3e38f;
#pragma unroll
            for (int j = 0; j < 8; j++) {
                int mt = j >> 1, rh = (j & 1) << 1;
                float x0 = acc[mt][nj][rh]     + b0f;
                float x1 = acc[mt][nj][rh + 1] + b1f;
                bool sameb = (bj[j] == bF);
                if (vj[j] && sameb)  { mA0 = fmaxf(mA0, x0); mA1 = fmaxf(mA1, x1); }
                if (vj[j] && !sameb) { mB0 = fmaxf(mB0, x0); mB1 = fmaxf(mB1, x1); }
            }
            if (mA0 > -3e38f) atomicMaxF(outp + (size_t)bF*EDIM + cc,     mA0);
            if (mA1 > -3e38f) atomicMaxF(outp + (size_t)bF*EDIM + cc + 1, mA1);
            if (bL != bF) {
                if (mB0 > -3e38f) atomicMaxF(outp + (size_t)bL*EDIM + cc,     mB0);
                if (mB1 > -3e38f) atomicMaxF(outp + (size_t)bL*EDIM + cc + 1, mB1);
            }
        }
        return;
    }

    /* ----------------------------- epilogue ------------------------------ */
    float sg = 0.f;
    if (EPI == 2) sg = 1.0f / (1.0f + expf(-gptr[0]));
    float st1[16], st2[16];
    if (STATS) {
#pragma unroll
        for (int i = 0; i < 16; i++) { st1[i] = 0.f; st2[i] = 0.f; }
    }

#pragma unroll
    for (int mt = 0; mt < 4; mt++) {
#pragma unroll
        for (int nj = 0; nj < 8; nj++) {
            int r  = m0 + wm + mt * 16 + gid;
            int cc = n0 + wn + nj * 8 + 2 * tig;
            float b0v = bias[cc], b1v = bias[cc + 1];
            float v[4];
            v[0] = acc[mt][nj][0] + b0v;
            v[1] = acc[mt][nj][1] + b1v;
            v[2] = acc[mt][nj][2] + b0v;
            v[3] = acc[mt][nj][3] + b1v;
            if (EPI == 1) {
#pragma unroll
                for (int c = 0; c < 4; c++)
                    v[c] = 0.5f * v[c] * (1.0f + erff(v[c] * 0.70710678118654752f));
            }
            if (EPI == 2) {
                const __half* auxh = (const __half*)aux;
                half2 a0 = *(const half2*)(auxh + (size_t)r * N + cc);
                half2 a1 = *(const half2*)(auxh + (size_t)(r + 8) * N + cc);
                v[0] = __low2float(a0)  + sg * v[0];
                v[1] = __high2float(a0) + sg * v[1];
                v[2] = __low2float(a1)  + sg * v[2];
                v[3] = __high2float(a1) + sg * v[3];
            }
            if (STATS) {
                st1[nj*2+0] += v[0] + v[2];
                st1[nj*2+1] += v[1] + v[3];
                st2[nj*2+0] += v[0]*v[0] + v[2]*v[2];
                st2[nj*2+1] += v[1]*v[1] + v[3]*v[3];
            }
            if (OUTH) {
                __half* Ch = (__half*)Cout;
                *(half2*)(Ch + (size_t)r * ldc + cc)       = __floats2half2_rn(v[0], v[1]);
                *(half2*)(Ch + (size_t)(r + 8) * ldc + cc) = __floats2half2_rn(v[2], v[3]);
            } else {
                float* Cf = (float*)Cout;
                *(float2*)(Cf + (size_t)r * ldc + cc)       = make_float2(v[0], v[1]);
                *(float2*)(Cf + (size_t)(r + 8) * ldc + cc) = make_float2(v[2], v[3]);
            }
        }
    }
    if (STATS) {
#pragma unroll
        for (int i = 0; i < 16; i++) {
            float a = st1[i], q = st2[i];
            a += __shfl_xor_sync(0xffffffffu, a, 4);
            a += __shfl_xor_sync(0xffffffffu, a, 8);
            a += __shfl_xor_sync(0xffffffffu, a, 16);
            q += __shfl_xor_sync(0xffffffffu, q, 4);
            q += __shfl_xor_sync(0xffffffffu, q, 8);
            q += __shfl_xor_sync(0xffffffffu, q, 16);
            if (gid == 0) {
                int col = n0 + wn + (i >> 1) * 8 + 2 * tig + (i & 1);
                atomicAdd(&g_s1[col], a);
                atomicAdd(&g_s2[col], q);
            }
        }
    }
}

/* ---------------- top-k selection (exact jax.lax.top_k order) ------------ */
__global__ void topk_kernel(const int* __restrict__ text,
                            const float* __restrict__ atten)
{
    int b = blockIdx.x;
    int t = threadIdx.x;            /* 512 threads */
    __shared__ float sval[NT];
    __shared__ int   sidx[NT];
    __shared__ int   red[NT];

    int tv = text[b*NT + t];

    red[t] = (tv << 10) | (NT - 1 - t);
    __syncthreads();
    for (int s = NT/2; s > 0; s >>= 1) {
        if (t < s) red[t] = max(red[t], red[t+s]);
        __syncthreads();
    }
    int eos = NT - 1 - (red[0] & 1023);
    __syncthreads();

    red[t] = (tv != 0) ? 1 : 0;
    __syncthreads();
    for (int s = NT/2; s > 0; s >>= 1) {
        if (t < s) red[t] += red[t+s];
        __syncthreads();
    }
    int nz = red[0];
    __syncthreads();

    float v;
    if (t == 0 || t == eos) v = -1.0f;
    else                    v = atten[((size_t)b*NT + eos)*NT + t];
    if (tv == 0) v = 0.0f;

    sval[t] = v; sidx[t] = t;
    __syncthreads();

    for (int ksz = 2; ksz <= NT; ksz <<= 1) {
        for (int j = ksz >> 1; j > 0; j >>= 1) {
            int ixj = t ^ j;
            if (ixj > t) {
                float va = sval[t], vb = sval[ixj];
                int   ia = sidx[t], ib = sidx[ixj];
                bool aBefore = (va > vb) || (va == vb && ia < ib);
                bool desc = ((t & ksz) == 0);
                if (desc ? !aBefore : aBefore) {
                    sval[t] = vb; sval[ixj] = va;
                    sidx[t] = ib; sidx[ixj] = ia;
                }
            }
            __syncthreads();
        }
    }
    if (t < KTOP) g_idx[b*KTOP + t] = sidx[t];
    if (t == 0) {
        int lnn = nz - 2;
        if (lnn > KTOP) lnn = KTOP;
        if (lnn < 1) lnn = 1;
        g_lens[b] = lnn;
    }
}

/* ---------- gather + L2 normalize + LayerNorm (warp per token) ----------- */
__global__ __launch_bounds__(256)
void gather_ln_kernel(const float* __restrict__ features,
                      const float* __restrict__ lnw,
                      const float* __restrict__ lnb)
{
    int warp = threadIdx.x >> 5;
    int lane = threadIdx.x & 31;
    int token = blockIdx.x * 8 + warp;           /* BKTOK = 4896*8 exact */
    int b = token / KTOP;
    int src = g_idx[token];
    const float* f = features + ((size_t)b*NT + src)*DIM;

    float4 v[4];
    float s1 = 0.f, s2 = 0.f;
#pragma unroll
    for (int q = 0; q < 4; q++) {
        v[q] = *(const float4*)(f + lane*4 + q*128);
        s1 += v[q].x + v[q].y + v[q].z + v[q].w;
        s2 += v[q].x*v[q].x + v[q].y*v[q].y + v[q].z*v[q].z + v[q].w*v[q].w;
    }
#pragma unroll
    for (int st = 16; st > 0; st >>= 1) {
        s1 += __shfl_xor_sync(0xffffffffu, s1, st);
        s2 += __shfl_xor_sync(0xffffffffu, s2, st);
    }
    float inv  = 1.0f / (sqrtf(s2) + 1e-6f);
    float mean = s1 * inv * (1.0f/DIM);
    float et2  = s2 * inv * inv * (1.0f/DIM);
    float var  = et2 - mean*mean;
    float rstd = rsqrtf(var + 1e-5f);

    __half* tokp = g_tokh0 + (size_t)token*DIM;
    __half* qp   = g_qh    + (size_t)token*DIM;
#pragma unroll
    for (int q = 0; q < 4; q++) {
        int c = lane*4 + q*128;
        float4 w4 = *(const float4*)(lnw + c);
        float4 b4 = *(const float4*)(lnb + c);
        float t0 = v[q].x * inv, t1 = v[q].y * inv;
        float t2 = v[q].z * inv, t3 = v[q].w * inv;
        *(half2*)(tokp + c)     = __floats2half2_rn(t0, t1);
        *(half2*)(tokp + c + 2) = __floats2half2_rn(t2, t3);
        half2 h0 = __floats2half2_rn((t0-mean)*rstd*w4.x + b4.x,
                                     (t1-mean)*rstd*w4.y + b4.y);
        half2 h1 = __floats2half2_rn((t2-mean)*rstd*w4.z + b4.z,
                                     (t3-mean)*rstd*w4.w + b4.w);
        *(half2*)(qp + c)     = h0;
        *(half2*)(qp + c + 2) = h1;
    }
}

/* ------------- tensor-core flash attention: one block per (b,h) ---------- */
__global__ __launch_bounds__(ATT_THREADS)
void attn_tc()
{
    const int h = blockIdx.x, b = blockIdx.y;
    extern __shared__ __half ash[];
    __half* sQ = ash;
    __half* sK = ash + ATT_ROWS*64;
    __half* sV = ash + 2*ATT_ROWS*64;
    const int tid = threadIdx.x;
    const int wid = tid >> 5, lane = tid & 31;
    const int gid = lane >> 2, tig = lane & 3;
    const size_t tokbase = (size_t)b * KTOP;
    const __half* qkv = g_qkvh;

    for (int i = tid; i < ATT_ROWS*8; i += ATT_THREADS) {
        int r = i >> 3, c = i & 7;
        uint4 zq = make_uint4(0,0,0,0), zk = zq, zv = zq;
        if (r < KTOP) {
            const __half* base = qkv + (tokbase + r)*1536 + h*64 + c*8;
            zq = *(const uint4*)(base);
            zk = *(const uint4*)(base + 512);
            zv = *(const uint4*)(base + 1024);
        }
        int off = r*64 + ((c ^ (r & 7)) << 3);
        *(uint4*)(sQ + off) = zq;
        *(uint4*)(sK + off) = zk;
        *(uint4*)(sV + off) = zv;
    }
    __syncthreads();

    const uint32_t uQ = smem_u32(sQ), uK = smem_u32(sK), uV = smem_u32(sV);
    const int wm = wid * 16;
    const int mrow = lane & 7, msel = lane >> 3;

    uint32_t aq[4][4];
    {
        int row = wm + mrow + ((msel & 1) << 3);
        int chalf = msel >> 1;
#pragma unroll
        for (int ks = 0; ks < 4; ks++) {
            int ch = 2*ks + chalf;
            ldsm4(aq[ks][0], aq[ks][1], aq[ks][2], aq[ks][3],
                  uQ + (uint32_t)(row*128 + ((ch ^ (row & 7)) << 4)));
        }
    }

    float mr0 = -1e30f, mr1 = -1e30f, l0 = 0.f, l1 = 0.f;
    float o[8][4];
#pragma unroll
    for (int i = 0; i < 8; i++)
#pragma unroll
        for (int c = 0; c < 4; c++) o[i][c] = 0.f;

#pragma unroll 1
    for (int kc = 0; kc < 3; kc++) {
        float sS[8][4];
#pragma unroll
        for (int i = 0; i < 8; i++)
#pragma unroll
            for (int c = 0; c < 4; c++) sS[i][c] = 0.f;

#pragma unroll
        for (int ks = 0; ks < 4; ks++) {
            int chalf = msel >> 1;
            int ch = 2*ks + chalf;
            int nro = mrow + ((msel & 1) << 3);
#pragma unroll
            for (int p = 0; p < 4; p++) {
                int nr = kc*64 + p*16 + nro;
                uint32_t r0, r1, r2, r3;
                ldsm4(r0, r1, r2, r3,
                      uK + (uint32_t)(nr*128 + ((ch ^ (nr & 7)) << 4)));
                mma_h(sS[2*p][0], sS[2*p][1], sS[2*p][2], sS[2*p][3],
                      aq[ks][0], aq[ks][1], aq[ks][2], aq[ks][3], r0, r2);
                mma_h(sS[2*p+1][0], sS[2*p+1][1], sS[2*p+1][2], sS[2*p+1][3],
                      aq[ks][0], aq[ks][1], aq[ks][2], aq[ks][3], r1, r3);
            }
        }

#pragma unroll
        for (int nf = 0; nf < 8; nf++)
#pragma unroll
            for (int c = 0; c < 4; c++) sS[nf][c] *= 0.125f;
        if (kc == 2) {
#pragma unroll
            for (int nf = 0; nf < 8; nf++) {
                int col = 128 + nf*8 + 2*tig;
                if (col     >= KTOP) { sS[nf][0] = -1e30f; sS[nf][2] = -1e30f; }
                if (col + 1 >= KTOP) { sS[nf][1] = -1e30f; sS[nf][3] = -1e30f; }
            }
        }

        float cm0 = -1e30f, cm1 = -1e30f;
#pragma unroll
        for (int nf = 0; nf < 8; nf++) {
            cm0 = fmaxf(cm0, fmaxf(sS[nf][0], sS[nf][1]));
            cm1 = fmaxf(cm1, fmaxf(sS[nf][2], sS[nf][3]));
        }
        cm0 = fmaxf(cm0, __shfl_xor_sync(0xffffffffu, cm0, 1));
        cm0 = fmaxf(cm0, __shfl_xor_sync(0xffffffffu, cm0, 2));
        cm1 = fmaxf(cm1, __shfl_xor_sync(0xffffffffu, cm1, 1));
        cm1 = fmaxf(cm1, __shfl_xor_sync(0xffffffffu, cm1, 2));
        float nm0 = fmaxf(mr0, cm0), nm1 = fmaxf(mr1, cm1);
        float f0 = __expf(mr0 - nm0), f1 = __expf(mr1 - nm1);
        mr0 = nm0; mr1 = nm1;

        float ls0 = 0.f, ls1 = 0.f;
#pragma unroll
        for (int nf = 0; nf < 8; nf++) {
            sS[nf][0] = __expf(sS[nf][0] - nm0);
            sS[nf][1] = __expf(sS[nf][1] - nm0);
            sS[nf][2] = __expf(sS[nf][2] - nm1);
            sS[nf][3] = __expf(sS[nf][3] - nm1);
            ls0 += sS[nf][0] + sS[nf][1];
            ls1 += sS[nf][2] + sS[nf][3];
        }
        ls0 += __shfl_xor_sync(0xffffffffu, ls0, 1);
        ls0 += __shfl_xor_sync(0xffffffffu, ls0, 2);
        ls1 += __shfl_xor_sync(0xffffffffu, ls1, 1);
        ls1 += __shfl_xor_sync(0xffffffffu, ls1, 2);
        l0 = l0*f0 + ls0;
        l1 = l1*f1 + ls1;
#pragma unroll
        for (int df = 0; df < 8; df++) {
            o[df][0] *= f0; o[df][1] *= f0;
            o[df][2] *= f1; o[df][3] *= f1;
        }

        uint32_t ap[4][4];
#pragma unroll
        for (int j = 0; j < 4; j++) {
            ap[j][0] = pack_h2(sS[2*j][0],   sS[2*j][1]);
            ap[j][1] = pack_h2(sS[2*j][2],   sS[2*j][3]);
            ap[j][2] = pack_h2(sS[2*j+1][0], sS[2*j+1][1]);
            ap[j][3] = pack_h2(sS[2*j+1][2], sS[2*j+1][3]);
        }

#pragma unroll
        for (int j = 0; j < 4; j++) {
            int kr = kc*64 + j*16 + mrow + ((msel & 1) << 3);
            int chalf = msel >> 1;
#pragma unroll
            for (int p = 0; p < 4; p++) {
                int ch = 2*p + chalf;
                uint32_t r0, r1, r2, r3;
                ldsm4t(r0, r1, r2, r3,
                       uV + (uint32_t)(kr*128 + ((ch ^ (kr & 7)) << 4)));
                mma_h(o[2*p][0], o[2*p][1], o[2*p][2], o[2*p][3],
                      ap[j][0], ap[j][1], ap[j][2], ap[j][3], r0, r1);
                mma_h(o[2*p+1][0], o[2*p+1][1], o[2*p+1][2], o[2*p+1][3],
                      ap[j][0], ap[j][1], ap[j][2], ap[j][3], r2, r3);
            }
        }
    }

    float inv0 = 1.0f / l0, inv1 = 1.0f / l1;
    int r0g = wm + gid, r1g = wm + gid + 8;
#pragma unroll
    for (int df = 0; df < 8; df++) {
        int d = df*8 + 2*tig;
        if (r0g < KTOP)
            *(half2*)(g_sa + (tokbase + r0g)*512 + h*64 + d) =
                __floats2half2_rn(o[df][0]*inv0, o[df][1]*inv0);
        if (r1g < KTOP)
            *(half2*)(g_sa + (tokbase + r1g)*512 + h*64 + d) =
                __floats2half2_rn(o[df][2]*inv1, o[df][3]*inv1);
    }
}

/* ------------- BatchNorm apply (stats finalized inline) ------------------ */
__global__ void bn_apply(const float* __restrict__ bnw, const float* __restrict__ bnb)
{
    size_t i = (size_t)blockIdx.x*256 + threadIdx.x;   /* over BKTOK*256 h2 */
    if (i < (size_t)BKTOK*256) {
        int c2 = (int)(i & 255);
        int c  = c2 * 2;
        size_t row = i >> 8;
        float m0 = g_s1[c  ] * (1.0f/BKTOK);
        float m1 = g_s1[c+1] * (1.0f/BKTOK);
        float r0 = rsqrtf(g_s2[c  ] * (1.0f/BKTOK) - m0*m0 + 1e-5f);
        float r1 = rsqrtf(g_s2[c+1] * (1.0f/BKTOK) - m1*m1 + 1e-5f);
        half2 hv = ((const half2*)g_hh)[i];
        float x0 = __low2float(hv), x1 = __high2float(hv);
        x0 = (x0 - m0) * r0 * bnw[c  ] + bnb[c  ];
        x1 = (x1 - m1) * r1 * bnw[c+1] + bnb[c+1];
        ((half2*)(g_comb + row*1024 + 512))[c2] =
            __floats2half2_rn(fmaxf(x0, 0.f), fmaxf(x1, 0.f));
    }
}

/* ------------------------------- launcher -------------------------------- */
extern "C" void kernel_launch(void* const* d_in, const int* in_sizes, int n_in,
                              void* d_out, int out_size)
{
    const float* features = (const float*)d_in[0];
    const int*   text     = (const int*)  d_in[1];
    const float* atten    = (const float*)d_in[2];
    const float* ln_q_w   = (const float*)d_in[3];
    const float* ln_q_b   = (const float*)d_in[4];
    const float* sa_in_w  = (const float*)d_in[5];
    const float* sa_in_b  = (const float*)d_in[6];
    const float* sa_out_w = (const float*)d_in[7];
    const float* sa_out_b = (const float*)d_in[8];
    const float* ref_w1   = (const float*)d_in[9];
    const float* ref_b1   = (const float*)d_in[10];
    const float* ref_w2   = (const float*)d_in[11];
    const float* ref_b2   = (const float*)d_in[12];
    const float* gscal    = (const float*)d_in[13];
    const float* lin_w    = (const float*)d_in[14];
    const float* lin_b    = (const float*)d_in[15];
    const float* mlp_w1   = (const float*)d_in[16];
    const float* mlp_b1   = (const float*)d_in[17];
    const float* bn_w     = (const float*)d_in[18];
    const float* bn_b     = (const float*)d_in[19];
    const float* mlp_w2   = (const float*)d_in[20];
    const float* mlp_b2   = (const float*)d_in[21];
    float* out = (float*)d_out;

    float *p_bfin, *p_bfuse, *p_zero;
    __half *p_tok0, *p_qh, *p_qkvh, *p_sa, *p_y1h, *p_comb, *p_hh;
    __half *w_sain, *w_soT, *w_ref1, *w_ref2, *w_mlp1, *w_fin, *w_fuse;
    cudaGetSymbolAddress((void**)&p_tok0, g_tokh0);
    cudaGetSymbolAddress((void**)&p_qh,   g_qh);
    cudaGetSymbolAddress((void**)&p_qkvh, g_qkvh);
    cudaGetSymbolAddress((void**)&p_sa,   g_sa);
    cudaGetSymbolAddress((void**)&p_y1h,  g_y1h);
    cudaGetSymbolAddress((void**)&p_comb, g_comb);
    cudaGetSymbolAddress((void**)&p_hh,   g_hh);
    cudaGetSymbolAddress((void**)&p_bfin, g_bias_fin);
    cudaGetSymbolAddress((void**)&p_bfuse, g_bfuse);
    cudaGetSymbolAddress((void**)&p_zero, g_zero512);
    cudaGetSymbolAddress((void**)&w_sain,  g_w_sain);
    cudaGetSymbolAddress((void**)&w_soT,   g_w_soT);
    cudaGetSymbolAddress((void**)&w_ref1,  g_w_ref1);
    cudaGetSymbolAddress((void**)&w_ref2,  g_w_ref2);
    cudaGetSymbolAddress((void**)&w_mlp1,  g_w_mlp1);
    cudaGetSymbolAddress((void**)&w_fin,   g_w_fin);
    cudaGetSymbolAddress((void**)&w_fuse,  g_w_fuse);

    cudaFuncSetAttribute(gemm_h16<0,1,0,0>, cudaFuncAttributeMaxDynamicSharedMemorySize, GEMM_SMEM);
    cudaFuncSetAttribute(gemm_h16<0,1,1,0>, cudaFuncAttributeMaxDynamicSharedMemorySize, GEMM_SMEM);
    cudaFuncSetAttribute(gemm_h16<1,1,0,0>, cudaFuncAttributeMaxDynamicSharedMemorySize, GEMM_SMEM);
    cudaFuncSetAttribute(gemm_h16<2,1,0,0>, cudaFuncAttributeMaxDynamicSharedMemorySize, GEMM_SMEM);
    cudaFuncSetAttribute(gemm_h16<0,0,0,1>, cudaFuncAttributeMaxDynamicSharedMemorySize, GEMM_SMEM);
    cudaFuncSetAttribute(attn_tc, cudaFuncAttributeMaxDynamicSharedMemorySize, ATT_SMEM);

    const int MROWS = BKTOK;             /* 39168 = 306*128 */

    /* weight cvt + stats zero + bias sums + out -inf init + fused-bias rows */
    cvt_all_kernel<<<CVTB + 1024, 256>>>(sa_in_w, sa_out_w, ref_w1, ref_w2,
                                         lin_w, mlp_w1, mlp_w2, lin_b, mlp_b2,
                                         sa_out_b, ref_b1, out);
    /* W_fuse = W_r1 @ W_so */
    gemm_h16<0,1,0,0><<<dim3(512/128, 1024/128), 128, GEMM_SMEM>>>(
        w_ref1, 512, w_soT, p_zero, w_fuse, 512, 1024, 512, 512, nullptr, nullptr);

    topk_kernel<<<BATCH, NT>>>(text, atten);
    gather_ln_kernel<<<BKTOK/8, 256>>>(features, ln_q_w, ln_q_b);

    /* qkv = LN(tok) @ sa_in_w^T + b  (half out) */
    gemm_h16<0,1,0,0><<<dim3(1536/128, MROWS/128), 128, GEMM_SMEM>>>(
        p_qh, 512, w_sain, sa_in_b, p_qkvh, 1536, MROWS, 1536, 512, nullptr, nullptr);
    attn_tc<<<dim3(NHEADS, BATCH), ATT_THREADS, ATT_SMEM>>>();

    /* y1 = gelu(sa @ W_fuse^T + b_fuse)  (half out) */
    gemm_h16<1,1,0,0><<<dim3(1024/128, MROWS/128), 128, GEMM_SMEM>>>(
        p_sa, 512, w_fuse, p_bfuse, p_y1h, 1024, MROWS, 1024, 512, nullptr, nullptr);
    /* comb[:,0:512] = tok_h + sigmoid(g)*(y1 @ ref_w2^T + b)  (half out) */
    gemm_h16<2,1,0,0><<<dim3(512/128, MROWS/128), 128, GEMM_SMEM>>>(
        p_y1h, 1024, w_ref2, ref_b2, p_comb, 1024, MROWS, 512, 1024, p_tok0, gscal);
    /* h = tok_h @ mlp_w1^T + b  (half out + fused BN stats) */
    gemm_h16<0,1,1,0><<<dim3(512/128, MROWS/128), 128, GEMM_SMEM>>>(
        p_comb, 1024, w_mlp1, mlp_b1, p_hh, 512, MROWS, 512, 512, nullptr, nullptr);
    bn_apply<<<(int)(((size_t)BKTOK*256 + 255)/256), 256>>>(bn_w, bn_b);

    /* feat GEMM with fused masked max-pool -> out (atomicMax) */
    gemm_h16<0,0,0,1><<<dim3(1024/128, MROWS/128), 128, GEMM_SMEM>>>(
        p_comb, 1024, w_fin, p_bfin, out, 1024, MROWS, 1024, 1024, nullptr, nullptr);
}

// round 17
// speedup vs baseline: 1.0255x; 1.0042x over previous
#include <cuda_runtime.h>
#include <cuda_fp16.h>
#include <math.h>
#include <stdint.h>

#define BATCH 256
#define NT 512
#define DIM 512
#define KTOP 153
#define BKTOK (BATCH*KTOP)      /* 39168 = 306*128 */
#define EDIM 1024
#define NHEADS 8

#define GEMM_SMEM (4*16384)     /* 4 stages x (A 8KB + B 8KB) */
#define ATT_THREADS 320
#define ATT_ROWS 192            /* padded tile rows (3 chunks of 64) */
#define ATT_SMEM (3*ATT_ROWS*64*2)   /* Q,K,V half tiles: 73728 B */

/* ---------------- scratch (device globals; no allocation) ---------------- */
__device__ int    g_lens[BATCH];
__device__ __half g_tokh0[(size_t)BKTOK*DIM];      /* half residual source */
__device__ __half g_qh[(size_t)BKTOK*DIM];         /* LN out (GEMM A) */
__device__ __half g_qkvh[(size_t)BKTOK*3*DIM];     /* half qkv */
__device__ __half g_sa[(size_t)BKTOK*DIM];
__device__ __half g_y1h[(size_t)BKTOK*2*DIM];
__device__ __half g_comb[(size_t)BKTOK*1024];      /* [tok_h | relu_bn_h] */
__device__ __half g_hh[(size_t)BKTOK*DIM];         /* pre-BN h (half) */
__device__ float  g_s1[512];
__device__ float  g_s2[512];
/* half-converted weights */
__device__ __half g_w_sain[1536*512];
__device__ __half g_w_soT[512*512];                /* sa_out_w transposed */
__device__ __half g_w_ref1[1024*512];
__device__ __half g_w_ref2[512*1024];
__device__ __half g_w_mlp1[512*512];
__device__ __half g_w_fin[1024*1024];              /* [lin_w | mlp_w2] */
__device__ __half g_w_fuse[1024*512];              /* W_r1 @ W_so */
__device__ float  g_bias_fin[1024];                /* lin_b + mlp_b2 */
__device__ float  g_bfuse[1024];                   /* W_r1 @ b_so + b_r1 */
__device__ float  g_zero512[512];

/* ------------------------------ helpers ---------------------------------- */
__device__ __forceinline__ uint32_t smem_u32(const void* p) {
    uint32_t a;
    asm("{ .reg .u64 t; cvta.to.shared.u64 t, %1; cvt.u32.u64 %0, t; }"
        : "=r"(a) : "l"(p));
    return a;
}
#define CP_ASYNC16(dst, src) \
    asm volatile("cp.async.cg.shared.global [%0], [%1], 16;" :: "r"(dst), "l"(src))
#define CP_COMMIT()  asm volatile("cp.async.commit_group;" ::: "memory")
#define CP_WAIT_2()  asm volatile("cp.async.wait_group 2;" ::: "memory")

__device__ __forceinline__ void ldsm4(uint32_t& r0, uint32_t& r1,
                                      uint32_t& r2, uint32_t& r3, uint32_t addr) {
    asm volatile("ldmatrix.sync.aligned.m8n8.x4.shared.b16 {%0,%1,%2,%3}, [%4];"
                 : "=r"(r0), "=r"(r1), "=r"(r2), "=r"(r3) : "r"(addr));
}
__device__ __forceinline__ void ldsm4t(uint32_t& r0, uint32_t& r1,
                                       uint32_t& r2, uint32_t& r3, uint32_t addr) {
    asm volatile("ldmatrix.sync.aligned.m8n8.x4.trans.shared.b16 {%0,%1,%2,%3}, [%4];"
                 : "=r"(r0), "=r"(r1), "=r"(r2), "=r"(r3) : "r"(addr));
}
__device__ __forceinline__ void mma_h(float& d0, float& d1, float& d2, float& d3,
                                      uint32_t a0, uint32_t a1, uint32_t a2, uint32_t a3,
                                      uint32_t b0, uint32_t b1)
{
    asm volatile(
        "mma.sync.aligned.m16n8k16.row.col.f32.f16.f16.f32 "
        "{%0,%1,%2,%3}, {%4,%5,%6,%7}, {%8,%9}, {%0,%1,%2,%3};"
        : "+f"(d0), "+f"(d1), "+f"(d2), "+f"(d3)
        : "r"(a0), "r"(a1), "r"(a2), "r"(a3), "r"(b0), "r"(b1));
}
__device__ __forceinline__ uint32_t pack_h2(float a, float b) {
    half2 h = __floats2half2_rn(a, b);
    return *(uint32_t*)&h;
}
/* exact order-independent float atomic max (sign-split trick) */
__device__ __forceinline__ void atomicMaxF(float* a, float v) {
    if (v >= 0.f) atomicMax((int*)a, __float_as_int(v));
    else          atomicMin((unsigned int*)a, __float_as_uint(v));
}

/* -- weight cvt + stats zero + bias sums + out-init + fused-bias rows ----- */
/* counts in half2 units */
#define P0 393216                 /* sain  1536x512 */
#define P1 (P0+131072)            /* saout  512x512 -> TRANSPOSED g_w_soT */
#define P2 (P1+262144)            /* ref1  1024x512 */
#define P3 (P2+262144)            /* ref2   512x1024 */
#define P4 (P3+262144)            /* lin   1024x512 -> fin cols 0..511 */
#define P5 (P4+131072)            /* mlp1   512x512 */
#define P6 (P5+262144)            /* mlp2  1024x512 -> fin cols 512..1023 */
#define CVTB ((P6 + 255) / 256)   /* 6656 */

__global__ void cvt_all_kernel(const float* s_sain, const float* s_saout,
                               const float* s_ref1, const float* s_ref2,
                               const float* s_lin,  const float* s_mlp1,
                               const float* s_mlp2,
                               const float* lin_b,  const float* mlp_b2,
                               const float* sa_out_b, const float* ref_b1,
                               float* __restrict__ out)
{
    int t = threadIdx.x;
    if (blockIdx.x >= CVTB) {
        /* fused-bias rows: b_fuse[row] = dot(ref_w1[row,:], sa_out_b) + ref_b1[row] */
        int row = blockIdx.x - CVTB;         /* 0..1023 */
        const float* wr = s_ref1 + (size_t)row * 512;
        float s = wr[t] * sa_out_b[t] + wr[t + 256] * sa_out_b[t + 256];
        __shared__ float red[256];
        red[t] = s;
        __syncthreads();
        for (int st = 128; st > 0; st >>= 1) {
            if (t < st) red[t] += red[t + st];
            __syncthreads();
        }
        if (t == 0) g_bfuse[row] = red[0] + ref_b1[row];
        return;
    }
    if (blockIdx.x == 0) {
        g_s1[t] = 0.f; g_s1[t+256] = 0.f;
        g_s2[t] = 0.f; g_s2[t+256] = 0.f;
        g_zero512[t] = 0.f; g_zero512[t+256] = 0.f;
    }
    if (blockIdx.x == 1) {
#pragma unroll
        for (int q = 0; q < 4; q++)
            g_bias_fin[t + q*256] = lin_b[t + q*256] + mlp_b2[t + q*256];
    }
    if (blockIdx.x < BATCH*EDIM/256)     /* init out to -inf (fused pool) */
        out[blockIdx.x * 256 + t] = __int_as_float(0xff800000);

    int i = blockIdx.x * 256 + t;
    if (i >= P6) return;
    if (i < P0) {
        float2 v = ((const float2*)s_sain)[i];
        ((half2*)g_w_sain)[i] = __floats2half2_rn(v.x, v.y);
    } else if (i < P1) {
        int o = i - P0;
        int k = o >> 8, c2 = o & 255;
        float2 v = ((const float2*)s_saout)[o];
        g_w_soT[(2*c2  )*512 + k] = __float2half_rn(v.x);
        g_w_soT[(2*c2+1)*512 + k] = __float2half_rn(v.y);
    } else if (i < P2) {
        int o = i - P1;
        float2 v = ((const float2*)s_ref1)[o];
        ((half2*)g_w_ref1)[o] = __floats2half2_rn(v.x, v.y);
    } else if (i < P3) {
        int o = i - P2;
        float2 v = ((const float2*)s_ref2)[o];
        ((half2*)g_w_ref2)[o] = __floats2half2_rn(v.x, v.y);
    } else if (i < P4) {
        int o = i - P3;
        int n = o >> 8, kk = o & 255;
        float2 v = ((const float2*)s_lin)[o];
        ((half2*)g_w_fin)[n*512 + kk] = __floats2half2_rn(v.x, v.y);
    } else if (i < P5) {
        int o = i - P4;
        float2 v = ((const float2*)s_mlp1)[o];
        ((half2*)g_w_mlp1)[o] = __floats2half2_rn(v.x, v.y);
    } else {
        int o = i - P5;
        int n = o >> 8, kk = o & 255;
        float2 v = ((const float2*)s_mlp2)[o];
        ((half2*)g_w_fin)[n*512 + 256 + kk] = __floats2half2_rn(v.x, v.y);
    }
}

/* ---- fp16 tensor-core GEMM (cp.async + ldmatrix): C = A @ W^T + bias ---- */
/* 128 threads, 4 warps, warp tile 64x64 (2x2 warp grid over 128x128 tile).  */
/* EPI: 0=bias 1=gelu(bias) 2=C=auxh+sigmoid(g)*(acc+bias) (aux is half)     */
/* OUTH: store half.  STATS: BN column sums.  POOL: fused masked max-pool.   */
template<int EPI, int OUTH, int STATS, int POOL>
__global__ __launch_bounds__(128, 2)
void gemm_h16(const __half* __restrict__ A, int lda,
              const __half* __restrict__ W,
              const float* __restrict__ bias, void* __restrict__ Cout, int ldc,
              int M, int N, int K,
              const void* __restrict__ aux, const float* __restrict__ gptr)
{
    extern __shared__ __half smh[];
    const int tid  = threadIdx.x;
    const int wid  = tid >> 5;           /* 0..3 */
    const int lane = tid & 31;
    const int gid  = lane >> 2;
    const int tig  = lane & 3;
    const int wm   = (wid & 1) * 64;
    const int wn   = (wid >> 1) * 64;
    const int m0   = blockIdx.y * 128;
    const int n0   = blockIdx.x * 128;

    const uint32_t sbase = smem_u32(smh);

    uint32_t sto[4];
    const __half* srcA[4];
    const __half* srcB[4];
#pragma unroll
    for (int q = 0; q < 4; q++) {
        int id  = tid + q * 128;
        int row = id >> 2, cc = id & 3;
        sto[q]  = (uint32_t)(row * 64 + ((cc ^ (row & 3)) << 4));
        srcA[q] = A + (size_t)(m0 + row) * lda + cc * 8;
        srcB[q] = W + (size_t)(n0 + row) * K + cc * 8;
    }

    uint32_t aOff[4], bOff[4];
#pragma unroll
    for (int mt = 0; mt < 4; mt++) {
        int r  = wm + mt * 16 + (lane & 15);
        int ch = lane >> 4;
        aOff[mt] = (uint32_t)(r * 64 + ((ch ^ (r & 3)) << 4));
    }
#pragma unroll
    for (int njp = 0; njp < 4; njp++) {
        int r  = wn + njp * 16 + (lane & 7) + ((lane >> 4) << 3);
        int ch = (lane >> 3) & 1;
        bOff[njp] = (uint32_t)(8192 + r * 64 + ((ch ^ (r & 3)) << 4));
    }

    float acc[4][8][4];
#pragma unroll
    for (int i = 0; i < 4; i++)
#pragma unroll
        for (int j = 0; j < 8; j++)
#pragma unroll
            for (int c = 0; c < 4; c++) acc[i][j][c] = 0.f;

    const int nch = K >> 5;

    auto load_chunk = [&](int c) {
        uint32_t sb = sbase + (uint32_t)(c & 3) * 16384u;
        size_t ko = (size_t)c * 32;
#pragma unroll
        for (int q = 0; q < 4; q++) {
            CP_ASYNC16(sb + sto[q],        srcA[q] + ko);
            CP_ASYNC16(sb + 8192 + sto[q], srcB[q] + ko);
        }
    };

    load_chunk(0); CP_COMMIT();
    load_chunk(1); CP_COMMIT();
    load_chunk(2); CP_COMMIT();

    for (int c = 0; c < nch; c++) {
        CP_WAIT_2();
        __syncthreads();
        if (c + 3 < nch) load_chunk(c + 3);
        CP_COMMIT();

        uint32_t stb = sbase + (uint32_t)(c & 3) * 16384u;
#pragma unroll
        for (int ks = 0; ks < 2; ks++) {
            const uint32_t kx = (uint32_t)(ks << 5);
            uint32_t af[4][4], bf[4][4];
#pragma unroll
            for (int mt = 0; mt < 4; mt++)
                ldsm4(af[mt][0], af[mt][1], af[mt][2], af[mt][3],
                      stb + (aOff[mt] ^ kx));
#pragma unroll
            for (int njp = 0; njp < 4; njp++)
                ldsm4(bf[njp][0], bf[njp][1], bf[njp][2], bf[njp][3],
                      stb + (bOff[njp] ^ kx));
#pragma unroll
            for (int mt = 0; mt < 4; mt++)
#pragma unroll
                for (int nj = 0; nj < 8; nj++) {
                    const int njp = nj >> 1, pr = (nj & 1) << 1;
                    mma_h(acc[mt][nj][0], acc[mt][nj][1], acc[mt][nj][2], acc[mt][nj][3],
                          af[mt][0], af[mt][1], af[mt][2], af[mt][3],
                          bf[njp][pr], bf[njp][pr + 1]);
                }
        }
    }

    /* -------------------- fused masked max-pool epilogue ----------------- */
    if (POOL) {
        const int base = m0 + wm + gid;
        int bj[8]; bool vj[8];
#pragma unroll
        for (int j = 0; j < 8; j++) {
            int R = base + 8*j;
            int bb = R / KTOP;
            bj[j] = bb;
            vj[j] = (R - bb*KTOP) < g_lens[bb];
        }
        float* outp = (float*)Cout;
        const int bF = bj[0], bL = bj[7];
#pragma unroll
        for (int nj = 0; nj < 8; nj++) {
            int cc = n0 + wn + nj*8 + 2*tig;
            float b0f = bias[cc], b1f = bias[cc + 1];
            float mA0 = -3e38f, mA1 = -3e38f, mB0 = -3e38f, mB1 = -3e38f;
#pragma unroll
            for (int j = 0; j < 8; j++) {
                int mt = j >> 1, rh = (j & 1) << 1;
                float x0 = acc[mt][nj][rh]     + b0f;
                float x1 = acc[mt][nj][rh + 1] + b1f;
                bool sameb = (bj[j] == bF);
                if (vj[j] && sameb)  { mA0 = fmaxf(mA0, x0); mA1 = fmaxf(mA1, x1); }
                if (vj[j] && !sameb) { mB0 = fmaxf(mB0, x0); mB1 = fmaxf(mB1, x1); }
            }
            if (mA0 > -3e38f) atomicMaxF(outp + (size_t)bF*EDIM + cc,     mA0);
            if (mA1 > -3e38f) atomicMaxF(outp + (size_t)bF*EDIM + cc + 1, mA1);
            if (bL != bF) {
                if (mB0 > -3e38f) atomicMaxF(outp + (size_t)bL*EDIM + cc,     mB0);
                if (mB1 > -3e38f) atomicMaxF(outp + (size_t)bL*EDIM + cc + 1, mB1);
            }
        }
        return;
    }

    /* ----------------------------- epilogue ------------------------------ */
    float sg = 0.f;
    if (EPI == 2) sg = 1.0f / (1.0f + expf(-gptr[0]));
    float st1[16], st2[16];
    if (STATS) {
#pragma unroll
        for (int i = 0; i < 16; i++) { st1[i] = 0.f; st2[i] = 0.f; }
    }

#pragma unroll
    for (int mt = 0; mt < 4; mt++) {
#pragma unroll
        for (int nj = 0; nj < 8; nj++) {
            int r  = m0 + wm + mt * 16 + gid;
            int cc = n0 + wn + nj * 8 + 2 * tig;
            float b0v = bias[cc], b1v = bias[cc + 1];
            float v[4];
            v[0] = acc[mt][nj][0] + b0v;
            v[1] = acc[mt][nj][1] + b1v;
            v[2] = acc[mt][nj][2] + b0v;
            v[3] = acc[mt][nj][3] + b1v;
            if (EPI == 1) {
#pragma unroll
                for (int c = 0; c < 4; c++)
                    v[c] = 0.5f * v[c] * (1.0f + erff(v[c] * 0.70710678118654752f));
            }
            if (EPI == 2) {
                const __half* auxh = (const __half*)aux;
                half2 a0 = *(const half2*)(auxh + (size_t)r * N + cc);
                half2 a1 = *(const half2*)(auxh + (size_t)(r + 8) * N + cc);
                v[0] = __low2float(a0)  + sg * v[0];
                v[1] = __high2float(a0) + sg * v[1];
                v[2] = __low2float(a1)  + sg * v[2];
                v[3] = __high2float(a1) + sg * v[3];
            }
            if (STATS) {
                st1[nj*2+0] += v[0] + v[2];
                st1[nj*2+1] += v[1] + v[3];
                st2[nj*2+0] += v[0]*v[0] + v[2]*v[2];
                st2[nj*2+1] += v[1]*v[1] + v[3]*v[3];
            }
            if (OUTH) {
                __half* Ch = (__half*)Cout;
                *(half2*)(Ch + (size_t)r * ldc + cc)       = __floats2half2_rn(v[0], v[1]);
                *(half2*)(Ch + (size_t)(r + 8) * ldc + cc) = __floats2half2_rn(v[2], v[3]);
            } else {
                float* Cf = (float*)Cout;
                *(float2*)(Cf + (size_t)r * ldc + cc)       = make_float2(v[0], v[1]);
                *(float2*)(Cf + (size_t)(r + 8) * ldc + cc) = make_float2(v[2], v[3]);
            }
        }
    }
    if (STATS) {
#pragma unroll
        for (int i = 0; i < 16; i++) {
            float a = st1[i], q = st2[i];
            a += __shfl_xor_sync(0xffffffffu, a, 4);
            a += __shfl_xor_sync(0xffffffffu, a, 8);
            a += __shfl_xor_sync(0xffffffffu, a, 16);
            q += __shfl_xor_sync(0xffffffffu, q, 4);
            q += __shfl_xor_sync(0xffffffffu, q, 8);
            q += __shfl_xor_sync(0xffffffffu, q, 16);
            if (gid == 0) {
                int col = n0 + wn + (i >> 1) * 8 + 2 * tig + (i & 1);
                atomicAdd(&g_s1[col], a);
                atomicAdd(&g_s2[col], q);
            }
        }
    }
}

/* -------- merged top-k (exact jax order) + gather + L2norm + LN ---------- */
__global__ __launch_bounds__(512)
void topk_gather_kernel(const int* __restrict__ text,
                        const float* __restrict__ atten,
                        const float* __restrict__ features,
                        const float* __restrict__ lnw,
                        const float* __restrict__ lnb)
{
    int b = blockIdx.x;
    int t = threadIdx.x;            /* 512 threads */
    __shared__ float sval[NT];
    __shared__ int   sidx[NT];
    __shared__ int   red[NT];

    int tv = text[b*NT + t];

    /* eos = argmax(text), first occurrence of max */
    red[t] = (tv << 10) | (NT - 1 - t);
    __syncthreads();
    for (int s = NT/2; s > 0; s >>= 1) {
        if (t < s) red[t] = max(red[t], red[t+s]);
        __syncthreads();
    }
    int eos = NT - 1 - (red[0] & 1023);
    __syncthreads();

    /* lengths = nnz - 2 */
    red[t] = (tv != 0) ? 1 : 0;
    __syncthreads();
    for (int s = NT/2; s > 0; s >>= 1) {
        if (t < s) red[t] += red[t+s];
        __syncthreads();
    }
    int nz = red[0];
    __syncthreads();

    float v;
    if (t == 0 || t == eos) v = -1.0f;
    else                    v = atten[((size_t)b*NT + eos)*NT + t];
    if (tv == 0) v = 0.0f;

    sval[t] = v; sidx[t] = t;
    __syncthreads();

    /* bitonic sort, key = (val desc, idx asc) */
    for (int ksz = 2; ksz <= NT; ksz <<= 1) {
        for (int j = ksz >> 1; j > 0; j >>= 1) {
            int ixj = t ^ j;
            if (ixj > t) {
                float va = sval[t], vb = sval[ixj];
                int   ia = sidx[t], ib = sidx[ixj];
                bool aBefore = (va > vb) || (va == vb && ia < ib);
                bool desc = ((t & ksz) == 0);
                if (desc ? !aBefore : aBefore) {
                    sval[t] = vb; sval[ixj] = va;
                    sidx[t] = ib; sidx[ixj] = ia;
                }
            }
            __syncthreads();
        }
    }
    if (t == 0) {
        int lnn = nz - 2;
        if (lnn > KTOP) lnn = KTOP;
        if (lnn < 1) lnn = 1;
        g_lens[b] = lnn;
    }
    __syncthreads();

    /* ---- phase 2: gather + L2 normalize + LayerNorm (warp per token) ---- */
    int warp = t >> 5;              /* 0..15 */
    int lane = t & 31;
    for (int tok = warp; tok < KTOP; tok += 16) {
        int src = sidx[tok];
        size_t token = (size_t)b * KTOP + tok;
        const float* f = features + ((size_t)b*NT + src)*DIM;

        float4 vv[4];
        float s1 = 0.f, s2 = 0.f;
#pragma unroll
        for (int q = 0; q < 4; q++) {
            vv[q] = *(const float4*)(f + lane*4 + q*128);
            s1 += vv[q].x + vv[q].y + vv[q].z + vv[q].w;
            s2 += vv[q].x*vv[q].x + vv[q].y*vv[q].y + vv[q].z*vv[q].z + vv[q].w*vv[q].w;
        }
#pragma unroll
        for (int st = 16; st > 0; st >>= 1) {
            s1 += __shfl_xor_sync(0xffffffffu, s1, st);
            s2 += __shfl_xor_sync(0xffffffffu, s2, st);
        }
        float inv  = 1.0f / (sqrtf(s2) + 1e-6f);
        float mean = s1 * inv * (1.0f/DIM);
        float et2  = s2 * inv * inv * (1.0f/DIM);
        float var  = et2 - mean*mean;
        float rstd = rsqrtf(var + 1e-5f);

        __half* tokp = g_tokh0 + token*DIM;
        __half* qp   = g_qh    + token*DIM;
#pragma unroll
        for (int q = 0; q < 4; q++) {
            int c = lane*4 + q*128;
            float4 w4 = *(const float4*)(lnw + c);
            float4 b4 = *(const float4*)(lnb + c);
            float t0 = vv[q].x * inv, t1 = vv[q].y * inv;
            float t2 = vv[q].z * inv, t3 = vv[q].w * inv;
            *(half2*)(tokp + c)     = __floats2half2_rn(t0, t1);
            *(half2*)(tokp + c + 2) = __floats2half2_rn(t2, t3);
            half2 h0 = __floats2half2_rn((t0-mean)*rstd*w4.x + b4.x,
                                         (t1-mean)*rstd*w4.y + b4.y);
            half2 h1 = __floats2half2_rn((t2-mean)*rstd*w4.z + b4.z,
                                         (t3-mean)*rstd*w4.w + b4.w);
            *(half2*)(qp + c)     = h0;
            *(half2*)(qp + c + 2) = h1;
        }
    }
}

/* ------------- tensor-core flash attention: one block per (b,h) ---------- */
__global__ __launch_bounds__(ATT_THREADS)
void attn_tc()
{
    const int h = blockIdx.x, b = blockIdx.y;
    extern __shared__ __half ash[];
    __half* sQ = ash;
    __half* sK = ash + ATT_ROWS*64;
    __half* sV = ash + 2*ATT_ROWS*64;
    const int tid = threadIdx.x;
    const int wid = tid >> 5, lane = tid & 31;
    const int gid = lane >> 2, tig = lane & 3;
    const size_t tokbase = (size_t)b * KTOP;
    const __half* qkv = g_qkvh;

    for (int i = tid; i < ATT_ROWS*8; i += ATT_THREADS) {
        int r = i >> 3, c = i & 7;
        uint4 zq = make_uint4(0,0,0,0), zk = zq, zv = zq;
        if (r < KTOP) {
            const __half* base = qkv + (tokbase + r)*1536 + h*64 + c*8;
            zq = *(const uint4*)(base);
            zk = *(const uint4*)(base + 512);
            zv = *(const uint4*)(base + 1024);
        }
        int off = r*64 + ((c ^ (r & 7)) << 3);
        *(uint4*)(sQ + off) = zq;
        *(uint4*)(sK + off) = zk;
        *(uint4*)(sV + off) = zv;
    }
    __syncthreads();

    const uint32_t uQ = smem_u32(sQ), uK = smem_u32(sK), uV = smem_u32(sV);
    const int wm = wid * 16;
    const int mrow = lane & 7, msel = lane >> 3;

    uint32_t aq[4][4];
    {
        int row = wm + mrow + ((msel & 1) << 3);
        int chalf = msel >> 1;
#pragma unroll
        for (int ks = 0; ks < 4; ks++) {
            int ch = 2*ks + chalf;
            ldsm4(aq[ks][0], aq[ks][1], aq[ks][2], aq[ks][3],
                  uQ + (uint32_t)(row*128 + ((ch ^ (row & 7)) << 4)));
        }
    }

    float mr0 = -1e30f, mr1 = -1e30f, l0 = 0.f, l1 = 0.f;
    float o[8][4];
#pragma unroll
    for (int i = 0; i < 8; i++)
#pragma unroll
        for (int c = 0; c < 4; c++) o[i][c] = 0.f;

#pragma unroll 1
    for (int kc = 0; kc < 3; kc++) {
        float sS[8][4];
#pragma unroll
        for (int i = 0; i < 8; i++)
#pragma unroll
            for (int c = 0; c < 4; c++) sS[i][c] = 0.f;

#pragma unroll
        for (int ks = 0; ks < 4; ks++) {
            int chalf = msel >> 1;
            int ch = 2*ks + chalf;
            int nro = mrow + ((msel & 1) << 3);
#pragma unroll
            for (int p = 0; p < 4; p++) {
                int nr = kc*64 + p*16 + nro;
                uint32_t r0, r1, r2, r3;
                ldsm4(r0, r1, r2, r3,
                      uK + (uint32_t)(nr*128 + ((ch ^ (nr & 7)) << 4)));
                mma_h(sS[2*p][0], sS[2*p][1], sS[2*p][2], sS[2*p][3],
                      aq[ks][0], aq[ks][1], aq[ks][2], aq[ks][3], r0, r2);
                mma_h(sS[2*p+1][0], sS[2*p+1][1], sS[2*p+1][2], sS[2*p+1][3],
                      aq[ks][0], aq[ks][1], aq[ks][2], aq[ks][3], r1, r3);
            }
        }

#pragma unroll
        for (int nf = 0; nf < 8; nf++)
#pragma unroll
            for (int c = 0; c < 4; c++) sS[nf][c] *= 0.125f;
        if (kc == 2) {
#pragma unroll
            for (int nf = 0; nf < 8; nf++) {
                int col = 128 + nf*8 + 2*tig;
                if (col     >= KTOP) { sS[nf][0] = -1e30f; sS[nf][2] = -1e30f; }
                if (col + 1 >= KTOP) { sS[nf][1] = -1e30f; sS[nf][3] = -1e30f; }
            }
        }

        float cm0 = -1e30f, cm1 = -1e30f;
#pragma unroll
        for (int nf = 0; nf < 8; nf++) {
            cm0 = fmaxf(cm0, fmaxf(sS[nf][0], sS[nf][1]));
            cm1 = fmaxf(cm1, fmaxf(sS[nf][2], sS[nf][3]));
        }
        cm0 = fmaxf(cm0, __shfl_xor_sync(0xffffffffu, cm0, 1));
        cm0 = fmaxf(cm0, __shfl_xor_sync(0xffffffffu, cm0, 2));
        cm1 = fmaxf(cm1, __shfl_xor_sync(0xffffffffu, cm1, 1));
        cm1 = fmaxf(cm1, __shfl_xor_sync(0xffffffffu, cm1, 2));
        float nm0 = fmaxf(mr0, cm0), nm1 = fmaxf(mr1, cm1);
        float f0 = __expf(mr0 - nm0), f1 = __expf(mr1 - nm1);
        mr0 = nm0; mr1 = nm1;

        float ls0 = 0.f, ls1 = 0.f;
#pragma unroll
        for (int nf = 0; nf < 8; nf++) {
            sS[nf][0] = __expf(sS[nf][0] - nm0);
            sS[nf][1] = __expf(sS[nf][1] - nm0);
            sS[nf][2] = __expf(sS[nf][2] - nm1);
            sS[nf][3] = __expf(sS[nf][3] - nm1);
            ls0 += sS[nf][0] + sS[nf][1];
            ls1 += sS[nf][2] + sS[nf][3];
        }
        ls0 += __shfl_xor_sync(0xffffffffu, ls0, 1);
        ls0 += __shfl_xor_sync(0xffffffffu, ls0, 2);
        ls1 += __shfl_xor_sync(0xffffffffu, ls1, 1);
        ls1 += __shfl_xor_sync(0xffffffffu, ls1, 2);
        l0 = l0*f0 + ls0;
        l1 = l1*f1 + ls1;
#pragma unroll
        for (int df = 0; df < 8; df++) {
            o[df][0] *= f0; o[df][1] *= f0;
            o[df][2] *= f1; o[df][3] *= f1;
        }

        uint32_t ap[4][4];
#pragma unroll
        for (int j = 0; j < 4; j++) {
            ap[j][0] = pack_h2(sS[2*j][0],   sS[2*j][1]);
            ap[j][1] = pack_h2(sS[2*j][2],   sS[2*j][3]);
            ap[j][2] = pack_h2(sS[2*j+1][0], sS[2*j+1][1]);
            ap[j][3] = pack_h2(sS[2*j+1][2], sS[2*j+1][3]);
        }

#pragma unroll
        for (int j = 0; j < 4; j++) {
            int kr = kc*64 + j*16 + mrow + ((msel & 1) << 3);
            int chalf = msel >> 1;
#pragma unroll
            for (int p = 0; p < 4; p++) {
                int ch = 2*p + chalf;
                uint32_t r0, r1, r2, r3;
                ldsm4t(r0, r1, r2, r3,
                       uV + (uint32_t)(kr*128 + ((ch ^ (kr & 7)) << 4)));
                mma_h(o[2*p][0], o[2*p][1], o[2*p][2], o[2*p][3],
                      ap[j][0], ap[j][1], ap[j][2], ap[j][3], r0, r1);
                mma_h(o[2*p+1][0], o[2*p+1][1], o[2*p+1][2], o[2*p+1][3],
                      ap[j][0], ap[j][1], ap[j][2], ap[j][3], r2, r3);
            }
        }
    }

    float inv0 = 1.0f / l0, inv1 = 1.0f / l1;
    int r0g = wm + gid, r1g = wm + gid + 8;
#pragma unroll
    for (int df = 0; df < 8; df++) {
        int d = df*8 + 2*tig;
        if (r0g < KTOP)
            *(half2*)(g_sa + (tokbase + r0g)*512 + h*64 + d) =
                __floats2half2_rn(o[df][0]*inv0, o[df][1]*inv0);
        if (r1g < KTOP)
            *(half2*)(g_sa + (tokbase + r1g)*512 + h*64 + d) =
                __floats2half2_rn(o[df][2]*inv1, o[df][3]*inv1);
    }
}

/* ------------- BatchNorm apply (stats finalized inline) ------------------ */
__global__ void bn_apply(const float* __restrict__ bnw, const float* __restrict__ bnb)
{
    size_t i = (size_t)blockIdx.x*256 + threadIdx.x;   /* over BKTOK*256 h2 */
    if (i < (size_t)BKTOK*256) {
        int c2 = (int)(i & 255);
        int c  = c2 * 2;
        size_t row = i >> 8;
        float m0 = g_s1[c  ] * (1.0f/BKTOK);
        float m1 = g_s1[c+1] * (1.0f/BKTOK);
        float r0 = rsqrtf(g_s2[c  ] * (1.0f/BKTOK) - m0*m0 + 1e-5f);
        float r1 = rsqrtf(g_s2[c+1] * (1.0f/BKTOK) - m1*m1 + 1e-5f);
        half2 hv = ((const half2*)g_hh)[i];
        float x0 = __low2float(hv), x1 = __high2float(hv);
        x0 = (x0 - m0) * r0 * bnw[c  ] + bnb[c  ];
        x1 = (x1 - m1) * r1 * bnw[c+1] + bnb[c+1];
        ((half2*)(g_comb + row*1024 + 512))[c2] =
            __floats2half2_rn(fmaxf(x0, 0.f), fmaxf(x1, 0.f));
    }
}

/* ------------------------------- launcher -------------------------------- */
extern "C" void kernel_launch(void* const* d_in, const int* in_sizes, int n_in,
                              void* d_out, int out_size)
{
    const float* features = (const float*)d_in[0];
    const int*   text     = (const int*)  d_in[1];
    const float* atten    = (const float*)d_in[2];
    const float* ln_q_w   = (const float*)d_in[3];
    const float* ln_q_b   = (const float*)d_in[4];
    const float* sa_in_w  = (const float*)d_in[5];
    const float* sa_in_b  = (const float*)d_in[6];
    const float* sa_out_w = (const float*)d_in[7];
    const float* sa_out_b = (const float*)d_in[8];
    const float* ref_w1   = (const float*)d_in[9];
    const float* ref_b1   = (const float*)d_in[10];
    const float* ref_w2   = (const float*)d_in[11];
    const float* ref_b2   = (const float*)d_in[12];
    const float* gscal    = (const float*)d_in[13];
    const float* lin_w    = (const float*)d_in[14];
    const float* lin_b    = (const float*)d_in[15];
    const float* mlp_w1   = (const float*)d_in[16];
    const float* mlp_b1   = (const float*)d_in[17];
    const float* bn_w     = (const float*)d_in[18];
    const float* bn_b     = (const float*)d_in[19];
    const float* mlp_w2   = (const float*)d_in[20];
    const float* mlp_b2   = (const float*)d_in[21];
    float* out = (float*)d_out;

    float *p_bfin, *p_bfuse, *p_zero;
    __half *p_tok0, *p_qh, *p_qkvh, *p_sa, *p_y1h, *p_comb, *p_hh;
    __half *w_sain, *w_soT, *w_ref1, *w_ref2, *w_mlp1, *w_fin, *w_fuse;
    cudaGetSymbolAddress((void**)&p_tok0, g_tokh0);
    cudaGetSymbolAddress((void**)&p_qh,   g_qh);
    cudaGetSymbolAddress((void**)&p_qkvh, g_qkvh);
    cudaGetSymbolAddress((void**)&p_sa,   g_sa);
    cudaGetSymbolAddress((void**)&p_y1h,  g_y1h);
    cudaGetSymbolAddress((void**)&p_comb, g_comb);
    cudaGetSymbolAddress((void**)&p_hh,   g_hh);
    cudaGetSymbolAddress((void**)&p_bfin, g_bias_fin);
    cudaGetSymbolAddress((void**)&p_bfuse, g_bfuse);
    cudaGetSymbolAddress((void**)&p_zero, g_zero512);
    cudaGetSymbolAddress((void**)&w_sain,  g_w_sain);
    cudaGetSymbolAddress((void**)&w_soT,   g_w_soT);
    cudaGetSymbolAddress((void**)&w_ref1,  g_w_ref1);
    cudaGetSymbolAddress((void**)&w_ref2,  g_w_ref2);
    cudaGetSymbolAddress((void**)&w_mlp1,  g_w_mlp1);
    cudaGetSymbolAddress((void**)&w_fin,   g_w_fin);
    cudaGetSymbolAddress((void**)&w_fuse,  g_w_fuse);

    cudaFuncSetAttribute(gemm_h16<0,1,0,0>, cudaFuncAttributeMaxDynamicSharedMemorySize, GEMM_SMEM);
    cudaFuncSetAttribute(gemm_h16<0,1,1,0>, cudaFuncAttributeMaxDynamicSharedMemorySize, GEMM_SMEM);
    cudaFuncSetAttribute(gemm_h16<1,1,0,0>, cudaFuncAttributeMaxDynamicSharedMemorySize, GEMM_SMEM);
    cudaFuncSetAttribute(gemm_h16<2,1,0,0>, cudaFuncAttributeMaxDynamicSharedMemorySize, GEMM_SMEM);
    cudaFuncSetAttribute(gemm_h16<0,0,0,1>, cudaFuncAttributeMaxDynamicSharedMemorySize, GEMM_SMEM);
    cudaFuncSetAttribute(attn_tc, cudaFuncAttributeMaxDynamicSharedMemorySize, ATT_SMEM);

    const int MROWS = BKTOK;             /* 39168 = 306*128 */

    /* weight cvt + stats zero + bias sums + out -inf init + fused-bias rows */
    cvt_all_kernel<<<CVTB + 1024, 256>>>(sa_in_w, sa_out_w, ref_w1, ref_w2,
                                         lin_w, mlp_w1, mlp_w2, lin_b, mlp_b2,
                                         sa_out_b, ref_b1, out);
    /* W_fuse = W_r1 @ W_so */
    gemm_h16<0,1,0,0><<<dim3(512/128, 1024/128), 128, GEMM_SMEM>>>(
        w_ref1, 512, w_soT, p_zero, w_fuse, 512, 1024, 512, 512, nullptr, nullptr);

    /* merged top-k + gather + L2norm + LN (one launch, indices stay in smem) */
    topk_gather_kernel<<<BATCH, NT>>>(text, atten, features, ln_q_w, ln_q_b);

    /* qkv = LN(tok) @ sa_in_w^T + b  (half out) */
    gemm_h16<0,1,0,0><<<dim3(1536/128, MROWS/128), 128, GEMM_SMEM>>>(
        p_qh, 512, w_sain, sa_in_b, p_qkvh, 1536, MROWS, 1536, 512, nullptr, nullptr);
    attn_tc<<<dim3(NHEADS, BATCH), ATT_THREADS, ATT_SMEM>>>();

    /* y1 = gelu(sa @ W_fuse^T + b_fuse)  (half out) */
    gemm_h16<1,1,0,0><<<dim3(1024/128, MROWS/128), 128, GEMM_SMEM>>>(
        p_sa, 512, w_fuse, p_bfuse, p_y1h, 1024, MROWS, 1024, 512, nullptr, nullptr);
    /* comb[:,0:512] = tok_h + sigmoid(g)*(y1 @ ref_w2^T + b)  (half out) */
    gemm_h16<2,1,0,0><<<dim3(512/128, MROWS/128), 128, GEMM_SMEM>>>(
        p_y1h, 1024, w_ref2, ref_b2, p_comb, 1024, MROWS, 512, 1024, p_tok0, gscal);
    /* h = tok_h @ mlp_w1^T + b  (half out + fused BN stats) */
    gemm_h16<0,1,1,0><<<dim3(512/128, MROWS/128), 128, GEMM_SMEM>>>(
        p_comb, 1024, w_mlp1, mlp_b1, p_hh, 512, MROWS, 512, 512, nullptr, nullptr);
    bn_apply<<<(int)(((size_t)BKTOK*256 + 255)/256), 256>>>(bn_w, bn_b);

    /* feat GEMM with fused masked max-pool -> out (atomicMax) */
    gemm_h16<0,0,0,1><<<dim3(1024/128, MROWS/128), 128, GEMM_SMEM>>>(
        p_comb, 1024, w_fin, p_bfin, out, 1024, MROWS, 1024, 1024, nullptr, nullptr);
}